// round 11
// baseline (speedup 1.0000x reference)
#include <cuda_runtime.h>
#include <cuda_bf16.h>
#include <math.h>

#define Vv 20000
#define Lh 128
#define Dd 256
#define DEMOd 70
#define HIDd 1024
#define Nn 2048
#define KC 32
#define SST64 68
#define SA 136     // bf16 operand panel stride (272B, 16B-aligned, conflict-free LDSM)
#define XK 384

typedef unsigned long long u64;
typedef unsigned int u32;

__device__ __forceinline__ u64 ffma2(u64 a, u64 b, u64 c) {
    u64 d; asm("fma.rn.f32x2 %0,%1,%2,%3;" : "=l"(d) : "l"(a), "l"(b), "l"(c)); return d;
}
__device__ __forceinline__ u64 splat2(float x) {
    u64 d; asm("mov.b64 %0,{%1,%1};" : "=l"(d) : "f"(x)); return d;
}
__device__ __forceinline__ u64 pk(float x, float y) {
    u64 d; asm("mov.b64 %0,{%1,%2};" : "=l"(d) : "f"(x), "f"(y)); return d;
}
__device__ __forceinline__ float2 unpk(u64 v) {
    float2 r; asm("mov.b64 {%0,%1},%2;" : "=f"(r.x), "=f"(r.y) : "l"(v)); return r;
}
__device__ __forceinline__ u32 pack_bf16(float lo, float hi) {
    u32 r; asm("cvt.rn.bf16x2.f32 %0, %1, %2;" : "=r"(r) : "f"(hi), "f"(lo)); return r;
}
__device__ __forceinline__ void mma_bf16(float* d, const u32* a, const u32* b) {
    asm volatile(
        "mma.sync.aligned.m16n8k16.row.col.f32.bf16.bf16.f32 "
        "{%0,%1,%2,%3},{%4,%5,%6,%7},{%8,%9},{%0,%1,%2,%3};"
        : "+f"(d[0]), "+f"(d[1]), "+f"(d[2]), "+f"(d[3])
        : "r"(a[0]), "r"(a[1]), "r"(a[2]), "r"(a[3]), "r"(b[0]), "r"(b[1]));
}
__device__ __forceinline__ void ldsm4(u32& r0, u32& r1, u32& r2, u32& r3, u32 a) {
    asm volatile("ldmatrix.sync.aligned.m8n8.x4.shared.b16 {%0,%1,%2,%3},[%4];"
                 : "=r"(r0), "=r"(r1), "=r"(r2), "=r"(r3) : "r"(a));
}
#define CP_ASYNC16(dst, src, sz) \
    asm volatile("cp.async.cg.shared.global [%0], [%1], 16, %2;" :: "r"(dst), "l"(src), "r"(sz))
#define CP_COMMIT() asm volatile("cp.async.commit_group;")
#define CP_WAIT0()  asm volatile("cp.async.wait_group 0;" ::: "memory")
#define CP_WAIT1()  asm volatile("cp.async.wait_group 1;" ::: "memory")

// ---------- device scratch ----------
__device__ __nv_bfloat16 g_E16[Vv * Dd];
__device__ __nv_bfloat16 g_EM16[Vv * Dd];
__device__ __nv_bfloat16 g_M16T[Dd * Dd];
__device__ __nv_bfloat16 g_Wv16[Dd * Dd];        // Wv straight bf16 [k][n]
__device__ __nv_bfloat16 g_W1rT[HIDd * Dd];      // W1[70:326]^T : [h][m]
__device__ __nv_bfloat16 g_WfT16[HIDd * XK];     // final combined weight^T [h][kk]
__device__ __nv_bfloat16 g_X16[Nn * XK];         // [demo | ebar | 0]
__device__ float g_part[Nn * 8];                 // partial logits
__device__ int g_perm[Nn];
__device__ unsigned int g_ctr;                   // k3b last-block counter (zero-init)

__device__ __forceinline__ u32 a_lane_off(int lane, int warpRow) {
    return (u32)((warpRow + (lane & 15)) * SA + ((lane >> 4) << 3));
}
__device__ __forceinline__ u32 b_lane_off(int lane) {
    return (u32)(((lane & 7) + ((lane >> 4) << 3)) * SA + (((lane >> 3) & 1) << 3));
}

__device__ __forceinline__ void mma_ks_dense(u32 aAddr, u32 bAddr, float acc[16][4],
                                             int ks0, int ks1) {
    for (int ks = ks0; ks < ks1; ks++) {
        u32 a[4]; ldsm4(a[0], a[1], a[2], a[3], aAddr + ks * 32);
#pragma unroll
        for (int nt2 = 0; nt2 < 8; nt2++) {
            u32 b[4]; ldsm4(b[0], b[1], b[2], b[3], bAddr + nt2 * (16 * SA * 2) + ks * 32);
            mma_bf16(acc[2 * nt2], a, b);
            mma_bf16(acc[2 * nt2 + 1], a, b + 2);
        }
    }
}

// masked variant: STATIC unroll, predicated (keeps acc in registers)
__device__ __forceinline__ void mma_ks_masked(u32 aAddr, u32 bAddr, float acc[16][4],
                                              int ks0, int ks1, int nt2max, int len) {
    for (int ks = ks0; ks < ks1; ks++) {
        u32 a[4]; ldsm4(a[0], a[1], a[2], a[3], aAddr + ks * 32);
#pragma unroll
        for (int nt2 = 0; nt2 < 8; nt2++) {
            if (nt2 < nt2max) {
                u32 b[4];
                ldsm4(b[0], b[1], b[2], b[3], bAddr + nt2 * (16 * SA * 2) + ks * 32);
                mma_bf16(acc[2 * nt2], a, b);
                if (nt2 * 16 + 8 < len) mma_bf16(acc[2 * nt2 + 1], a, b + 2);
            }
        }
    }
}

// ============ merged prep kernel ============
// [0,16) k0_M | [16,1266) e16 x4 | [1266,1282) wv16 x4 | [1282,1666) w1T-split
// [1666,2690) x16 demo+zeros | 2690 sort
__global__ __launch_bounds__(256) void k_prep(
    const float* __restrict__ E, const float* __restrict__ Wq,
    const float* __restrict__ Wk, const float* __restrict__ Wv,
    const float* __restrict__ W1, const float* __restrict__ demo,
    const int* __restrict__ lengths) {
    extern __shared__ __align__(16) char psm[];
    int b = blockIdx.x, tid = threadIdx.x;

    if (b < 16) {                     // ---- M16T = (Wq Wk^T / 16)^T bf16
        float* As = (float*)psm;
        float* Bs = As + KC * SST64;
        int r0 = (b & 3) * 64, c0 = (b >> 2) * 64;
        int ty = tid >> 4, tx = tid & 15;
        int i0 = ty * 4, j0 = tx * 4;
        u64 acc[2][4];
#pragma unroll
        for (int a = 0; a < 2; a++)
#pragma unroll
            for (int c = 0; c < 4; c++) acc[a][c] = splat2(0.f);
        for (int k0 = 0; k0 < Dd; k0 += KC) {
            __syncthreads();
#pragma unroll
            for (int r = 0; r < 8; r++) {
                int idx = tid + r * 256;
                int i = idx >> 5, k = idx & 31;
                As[k * SST64 + i] = Wq[(r0 + i) * Dd + k0 + k];
                Bs[k * SST64 + i] = Wk[(c0 + i) * Dd + k0 + k];
            }
            __syncthreads();
#pragma unroll
            for (int k = 0; k < KC; k++) {
                float4 a0 = *(const float4*)(As + k * SST64 + i0);
                float4 b0 = *(const float4*)(Bs + k * SST64 + j0);
                u64 av[2] = {pk(a0.x, a0.y), pk(a0.z, a0.w)};
                float bv[4] = {b0.x, b0.y, b0.z, b0.w};
#pragma unroll
                for (int cc = 0; cc < 4; cc++) {
                    u64 bs = splat2(bv[cc]);
#pragma unroll
                    for (int a = 0; a < 2; a++) acc[a][cc] = ffma2(av[a], bs, acc[a][cc]);
                }
            }
        }
        const float sc = 1.0f / 16.0f;
#pragma unroll
        for (int a = 0; a < 2; a++)
#pragma unroll
            for (int c = 0; c < 4; c++) {
                float2 v = unpk(acc[a][c]);
                int row = r0 + i0 + 2 * a, col = c0 + j0 + c;
                g_M16T[col * Dd + row]     = __float2bfloat16(v.x * sc);
                g_M16T[col * Dd + row + 1] = __float2bfloat16(v.y * sc);
            }
    } else if (b < 1266) {            // ---- e16 (4 float4 per thread)
        int base = (b - 16) * 1024;
#pragma unroll
        for (int j = 0; j < 4; j++) {
            int idx = base + j * 256 + tid;
            float4 v = ((const float4*)E)[idx];
            uint2 o;
            o.x = pack_bf16(v.x, v.y);
            o.y = pack_bf16(v.z, v.w);
            ((uint2*)g_E16)[idx] = o;
        }
    } else if (b < 1282) {            // ---- Wv convert (4 float4 per thread)
        int base = (b - 1266) * 1024;
#pragma unroll
        for (int j = 0; j < 4; j++) {
            int idx = base + j * 256 + tid;
            float4 v = ((const float4*)Wv)[idx];
            uint2 o;
            o.x = pack_bf16(v.x, v.y);
            o.y = pack_bf16(v.z, v.w);
            ((uint2*)g_Wv16)[idx] = o;
        }
    } else if (b < 1666) {            // ---- W1^T split: demo cols -> WfT, repr rows -> W1rT
        float* t = (float*)psm;
        int local = b - 1282;
        int k0 = (local % 12) * 32, h0 = (local / 12) * 32;
        int tx = tid & 31, ty = tid >> 5;
#pragma unroll
        for (int i = 0; i < 4; i++) {
            int k = k0 + ty + i * 8;
            t[(ty + i * 8) * 33 + tx] = (k < DEMOd + Dd) ? W1[k * HIDd + h0 + tx] : 0.f;
        }
        __syncthreads();
#pragma unroll
        for (int i = 0; i < 4; i++) {
            int h = h0 + ty + i * 8;
            int kk = k0 + tx;
            float v = t[tx * 33 + ty + i * 8];
            if (kk < DEMOd)
                g_WfT16[h * XK + kk] = __float2bfloat16(v);
            else if (kk < DEMOd + Dd)
                g_W1rT[h * Dd + kk - DEMOd] = __float2bfloat16(v);
            else
                g_WfT16[h * XK + kk] = __float2bfloat16(0.f);
        }
    } else if (b < 2690) {            // ---- X16 demo cols + zero pad
        int local = b - 1666;
        int r = local * 2 + (tid >> 7);
        int t = tid & 127;
        if (t < DEMOd) g_X16[r * XK + t] = __float2bfloat16(demo[r * DEMOd + t]);
        else           g_X16[r * XK + 256 + t] = __float2bfloat16(0.f);   // 326..383
    } else {                          // ---- LPT sort
        __shared__ int hist[129], base[129];
        for (int c = tid; c < 129; c += 256) hist[c] = 0;
        __syncthreads();
        for (int i = tid; i < Nn; i += 256) atomicAdd(&hist[128 - lengths[i]], 1);
        __syncthreads();
        if (tid == 0) { int s = 0; for (int c = 0; c < 129; c++) { base[c] = s; s += hist[c]; } }
        __syncthreads();
        for (int i = tid; i < Nn; i += 256) {
            int pos = atomicAdd(&base[128 - lengths[i]], 1);
            g_perm[pos] = i;
        }
    }
}

// ---- K1x: blocks [0,314) EM GEMM, [314,330) Wcomb GEMM ----
__global__ __launch_bounds__(256, 2) void k1x() {
    extern __shared__ __align__(16) char smraw[];
    __nv_bfloat16* Asm = (__nv_bfloat16*)smraw;
    __nv_bfloat16* Bsm = Asm + 128 * SA;
    u32 smA = (u32)__cvta_generic_to_shared(Asm);
    u32 smB = (u32)__cvta_generic_to_shared(Bsm);

    int bx = blockIdx.x;
    int tid = threadIdx.x;
    int w = tid >> 5, lane = tid & 31;
    int g = lane >> 2, c4 = lane & 3;
    int warpRow = w * 16;
    u32 aAddr = smA + a_lane_off(lane, warpRow) * 2;
    u32 bAddr = smB + b_lane_off(lane) * 2;

    float acc[16][4];
#pragma unroll
    for (int t = 0; t < 16; t++)
        acc[t][0] = acc[t][1] = acc[t][2] = acc[t][3] = 0.f;

    if (bx < 314) {                   // ======== EM16 = E16 @ M ========
        int r0 = (bx % 157) * 128, c0 = (bx / 157) * 128;
        for (int p = 0; p < 2; p++) {
            __syncthreads();
#pragma unroll
            for (int half = 0; half < 2; half++) {
#pragma unroll
                for (int it = 0; it < 4; it++) {
                    int id = tid + it * 256;
                    int row = id >> 3, seg = (id & 7) + half * 8;
                    int ra = r0 + row;
                    const char* gA = (const char*)(g_E16 + (size_t)ra * Dd + p * 128) + seg * 16;
                    const char* gB = (const char*)(g_M16T + (size_t)(c0 + row) * Dd + p * 128) + seg * 16;
                    u32 off = (u32)(row * SA + seg * 8) * 2;
                    CP_ASYNC16(smA + off, gA, (ra < Vv) ? 16 : 0);
                    CP_ASYNC16(smB + off, gB, 16);
                }
                CP_COMMIT();
            }
            CP_WAIT1();
            __syncthreads();
            mma_ks_dense(aAddr, bAddr, acc, 0, 4);
            CP_WAIT0();
            __syncthreads();
            mma_ks_dense(aAddr, bAddr, acc, 4, 8);
        }
        int rr0 = r0 + warpRow + g, rr1 = rr0 + 8;
#pragma unroll
        for (int nt = 0; nt < 16; nt++) {
            int cc = c0 + nt * 8 + c4 * 2;
            if (rr0 < Vv)
                *(u32*)(g_EM16 + (size_t)rr0 * Dd + cc) = pack_bf16(acc[nt][0], acc[nt][1]);
            if (rr1 < Vv)
                *(u32*)(g_EM16 + (size_t)rr1 * Dd + cc) = pack_bf16(acc[nt][2], acc[nt][3]);
        }
    } else {                          // ======== WfT[:,70:326) = (Wv @ W1r)^T ========
        int bb = bx - 314;
        int h0 = (bb & 7) * 128, k0 = (bb >> 3) * 128;
        for (int p = 0; p < 2; p++) {
            __syncthreads();
#pragma unroll
            for (int it = 0; it < 8; it++) {
                int id = tid + it * 256;
                int row = id >> 4, seg = id & 15;
                const char* gA = (const char*)(g_W1rT + (size_t)(h0 + row) * Dd + p * 128) + seg * 16;
                const char* gB = (const char*)(g_Wv16 + (size_t)(k0 + row) * Dd + p * 128) + seg * 16;
                CP_ASYNC16(smA + (row * SA + seg * 8) * 2, gA, 16);
                CP_ASYNC16(smB + (row * SA + seg * 8) * 2, gB, 16);
            }
            CP_COMMIT(); CP_WAIT0();
            __syncthreads();
            mma_ks_dense(aAddr, bAddr, acc, 0, 8);
        }
        int rr0 = h0 + warpRow + g, rr1 = rr0 + 8;
#pragma unroll
        for (int nt = 0; nt < 16; nt++) {
            int cc = DEMOd + k0 + nt * 8 + c4 * 2;
            *(u32*)(g_WfT16 + (size_t)rr0 * XK + cc) = pack_bf16(acc[nt][0], acc[nt][1]);
            *(u32*)(g_WfT16 + (size_t)rr1 * XK + cc) = pack_bf16(acc[nt][2], acc[nt][3]);
        }
    }
}

// ---- K2: per-sample attention + pooling -> X16[:,70:326).  grid 2048 ----
__global__ __launch_bounds__(256, 2) void k2_attn(
    const int* __restrict__ codes,
    const float* __restrict__ ht, const float* __restrict__ et,
    const int* __restrict__ lengths, const float* __restrict__ c_attn,
    const float* __restrict__ c_pool) {
    extern __shared__ __align__(16) char smraw[];
    __nv_bfloat16* Asm = (__nv_bfloat16*)smraw;
    __nv_bfloat16* Bsm = Asm + 128 * SA;
    float* cs = (float*)(Bsm + 128 * SA);
    float* wv = cs + 8 * 128;
    float* pv = wv + 128;
    float* tv = pv + 128;
    int*   cd = (int*)(tv + 128);
    u32 smA = (u32)__cvta_generic_to_shared(Asm);
    u32 smB = (u32)__cvta_generic_to_shared(Bsm);

    int n = g_perm[blockIdx.x];
    int tid = threadIdx.x;
    int len = lengths[n];
    int w = tid >> 5, lane = tid & 31;
    int g = lane >> 2, c4 = lane & 3;

    if (tid < 128) {
        cd[tid] = codes[n * Lh + tid];
        tv[tid] = ht[n * Lh + tid];
        wv[tid] = 0.f;
    }
    __syncthreads();

    if (tid < 32) {
        float cp = c_pool[0], e_t = et[n];
        float ssum = 0.f;
        for (int i = tid; i < len; i += 32) {
            float e = __expf(-cp * (e_t - tv[i]));
            wv[i] = e; ssum += e;
        }
#pragma unroll
        for (int o = 16; o; o >>= 1) ssum += __shfl_xor_sync(~0u, ssum, o);
        float inv = 1.f / ssum;
        for (int i = tid; i < len; i += 32) wv[i] *= inv;
    }

    int warpRow = w * 16;
    bool wact = warpRow < len;
    int lim = (len + 15) & ~15;
    int nt2max = (len + 15) >> 4;
    u32 aAddr = smA + a_lane_off(lane, warpRow) * 2;
    u32 bAddr = smB + b_lane_off(lane) * 2;

    float acc[16][4];
#pragma unroll
    for (int t = 0; t < 16; t++)
        acc[t][0] = acc[t][1] = acc[t][2] = acc[t][3] = 0.f;

    for (int p = 0; p < 2; p++) {
        __syncthreads();
#pragma unroll
        for (int half = 0; half < 2; half++) {
#pragma unroll
            for (int it = 0; it < 4; it++) {
                int id = tid + it * 256;
                int row = id >> 3, seg = (id & 7) + half * 8;
                if (row < lim) {
                    int c = cd[row];
                    const char* gA = (const char*)(g_EM16 + (size_t)c * Dd + p * 128) + seg * 16;
                    const char* gB = (const char*)(g_E16 + (size_t)c * Dd + p * 128) + seg * 16;
                    u32 off = (u32)(row * SA + seg * 8) * 2;
                    int sz = (row < len) ? 16 : 0;
                    CP_ASYNC16(smA + off, gA, sz);
                    CP_ASYNC16(smB + off, gB, sz);
                }
            }
            CP_COMMIT();
        }
        CP_WAIT1();
        __syncthreads();
        if (wact) mma_ks_masked(aAddr, bAddr, acc, 0, 4, nt2max, len);
        CP_WAIT0();
        __syncthreads();
        if (wact) mma_ks_masked(aAddr, bAddr, acc, 4, 8, nt2max, len);
    }

    // reload E16 k-half0 into Asm, overlapped with the softmax below
    __syncthreads();
#pragma unroll
    for (int it = 0; it < 8; it++) {
        int id = tid + it * 256;
        int row = id >> 4, seg = id & 15;
        if (row < lim) {
            int c = cd[row];
            const char* gB = (const char*)(g_E16 + (size_t)c * Dd) + seg * 16;
            int sz = (row < len) ? 16 : 0;
            CP_ASYNC16(smA + (u32)(row * SA + seg * 8) * 2, gB, sz);
        }
    }
    CP_COMMIT();

    float sc0 = 0.f, sc1 = 0.f;
    if (wact) {
        float ca = c_attn[0];
        int r0 = warpRow + g, r1 = r0 + 8;
        float ti0 = tv[r0], ti1 = tv[r1];
        float s0 = 0.f, s1 = 0.f;
#pragma unroll
        for (int nt = 0; nt < 16; nt++) {
            int j0 = nt * 8 + c4 * 2;
            if (nt * 8 < len) {
                float tj0 = tv[j0], tj1 = tv[j0 + 1];
                float e00 = (j0     < len) ? __expf(acc[nt][0] - ca * fabsf(ti0 - tj0)) : 0.f;
                float e01 = (j0 + 1 < len) ? __expf(acc[nt][1] - ca * fabsf(ti0 - tj1)) : 0.f;
                float e10 = (j0     < len) ? __expf(acc[nt][2] - ca * fabsf(ti1 - tj0)) : 0.f;
                float e11 = (j0 + 1 < len) ? __expf(acc[nt][3] - ca * fabsf(ti1 - tj1)) : 0.f;
                acc[nt][0] = e00; acc[nt][1] = e01; acc[nt][2] = e10; acc[nt][3] = e11;
                s0 += e00 + e01; s1 += e10 + e11;
            }
        }
        s0 += __shfl_xor_sync(~0u, s0, 1); s0 += __shfl_xor_sync(~0u, s0, 2);
        s1 += __shfl_xor_sync(~0u, s1, 1); s1 += __shfl_xor_sync(~0u, s1, 2);
        sc0 = wv[r0] / s0;
        sc1 = wv[r1] / s1;
    }

#pragma unroll
    for (int nt = 0; nt < 16; nt++) {
        float v0 = 0.f, v1 = 0.f;
        if (wact && nt * 8 < len) {
            v0 = acc[nt][0] * sc0 + acc[nt][2] * sc1;
            v1 = acc[nt][1] * sc0 + acc[nt][3] * sc1;
        }
        v0 += __shfl_xor_sync(~0u, v0, 4);  v1 += __shfl_xor_sync(~0u, v1, 4);
        v0 += __shfl_xor_sync(~0u, v0, 8);  v1 += __shfl_xor_sync(~0u, v1, 8);
        v0 += __shfl_xor_sync(~0u, v0, 16); v1 += __shfl_xor_sync(~0u, v1, 16);
        if (g == 0) {
            int j0 = nt * 8 + c4 * 2;
            cs[w * 128 + j0] = v0;
            cs[w * 128 + j0 + 1] = v1;
        }
    }
    __syncthreads();
    if (tid < 128) {
        float p = 0.f;
#pragma unroll
        for (int q = 0; q < 8; q++) p += cs[q * 128 + tid];
        pv[tid] = p;
    }
    CP_WAIT0();
    __syncthreads();

    // ebar_d -> X16[n][70 + d]
    const __nv_bfloat16* base = (tid < 128) ? (Asm + tid) : (Bsm + (tid - 128));
    float a = 0.f;
#pragma unroll 4
    for (int j = 0; j < len; j++)
        a = fmaf(pv[j], __bfloat162float(base[j * SA]), a);
    g_X16[(size_t)n * XK + DEMOd + tid] = __float2bfloat16(a);
}

// ---- K3b: partial logits + fused final reduce.  grid (16,8), double-buffered ----
__global__ __launch_bounds__(256, 1) void k3b_H(
    const float* __restrict__ b1, const float* __restrict__ W2,
    const float* __restrict__ labels, const float* __restrict__ b2,
    const float* __restrict__ c_attn, const float* __restrict__ c_pool,
    float* __restrict__ out) {
    extern __shared__ __align__(16) char smraw[];
    // two (A,B) panel pairs
    __nv_bfloat16* buf = (__nv_bfloat16*)smraw;
    u32 smBase = (u32)__cvta_generic_to_shared(buf);
    const u32 PANEL = 128 * SA * 2;               // bytes per panel
    u32 smA[2] = {smBase, smBase + 2 * PANEL};
    u32 smB[2] = {smBase + PANEL, smBase + 3 * PANEL};

    __shared__ bool isLast;
    __shared__ float red[256];

    int r0 = blockIdx.x * 128, c0 = blockIdx.y * 128;
    int tid = threadIdx.x;
    int w = tid >> 5, lane = tid & 31;
    int g = lane >> 2, c4 = lane & 3;
    int warpRow = w * 16;
    u32 aOff = a_lane_off(lane, warpRow) * 2;
    u32 bOff = b_lane_off(lane) * 2;

    float acc[16][4];
#pragma unroll
    for (int t = 0; t < 16; t++)
        acc[t][0] = acc[t][1] = acc[t][2] = acc[t][3] = 0.f;

    // issue panel 0 load
#pragma unroll
    for (int it = 0; it < 8; it++) {
        int id = tid + it * 256;
        int row = id >> 4, seg = id & 15;
        const char* gA = (const char*)(g_X16 + (size_t)(r0 + row) * XK) + seg * 16;
        const char* gB = (const char*)(g_WfT16 + (size_t)(c0 + row) * XK) + seg * 16;
        CP_ASYNC16(smA[0] + (row * SA + seg * 8) * 2, gA, 16);
        CP_ASYNC16(smB[0] + (row * SA + seg * 8) * 2, gB, 16);
    }
    CP_COMMIT();

    for (int p = 0; p < 3; p++) {
        __syncthreads();   // previous compute done before overwriting that buffer
        if (p < 2) {
            int nb = (p + 1) & 1;
#pragma unroll
            for (int it = 0; it < 8; it++) {
                int id = tid + it * 256;
                int row = id >> 4, seg = id & 15;
                const char* gA = (const char*)(g_X16 + (size_t)(r0 + row) * XK + (p + 1) * 128) + seg * 16;
                const char* gB = (const char*)(g_WfT16 + (size_t)(c0 + row) * XK + (p + 1) * 128) + seg * 16;
                CP_ASYNC16(smA[nb] + (row * SA + seg * 8) * 2, gA, 16);
                CP_ASYNC16(smB[nb] + (row * SA + seg * 8) * 2, gB, 16);
            }
            CP_COMMIT();
            CP_WAIT1();
        } else {
            CP_WAIT0();
        }
        __syncthreads();
        int cb = p & 1;
        mma_ks_dense(smA[cb] + aOff, smB[cb] + bOff, acc, 0, 8);
    }

    int rr0 = r0 + warpRow + g, rr1 = rr0 + 8;
    float p0 = 0.f, p1 = 0.f;
#pragma unroll
    for (int nt = 0; nt < 16; nt++) {
        int col = c0 + nt * 8 + c4 * 2;
        float bb0 = b1[col], bb1 = b1[col + 1];
        float w0 = W2[col], w1 = W2[col + 1];
        p0 += fmaxf(acc[nt][0] + bb0, 0.f) * w0 + fmaxf(acc[nt][1] + bb1, 0.f) * w1;
        p1 += fmaxf(acc[nt][2] + bb0, 0.f) * w0 + fmaxf(acc[nt][3] + bb1, 0.f) * w1;
    }
    p0 += __shfl_xor_sync(~0u, p0, 1); p0 += __shfl_xor_sync(~0u, p0, 2);
    p1 += __shfl_xor_sync(~0u, p1, 1); p1 += __shfl_xor_sync(~0u, p1, 2);
    if (c4 == 0) {
        g_part[rr0 * 8 + blockIdx.y] = p0;
        g_part[rr1 * 8 + blockIdx.y] = p1;
    }

    // ---- fused final reduce (classic last-block pattern) ----
    __threadfence();
    __syncthreads();
    if (tid == 0) {
        unsigned int old = atomicAdd(&g_ctr, 1u);
        isLast = (old == 16 * 8 - 1);
    }
    __syncthreads();
    if (isLast) {
        float s = 0.f;
        for (int i = tid; i < Nn; i += 256) {
            float lg = b2[0];
#pragma unroll
            for (int q = 0; q < 8; q++) lg += g_part[i * 8 + q];
            float y = labels[i];
            float sp = (lg > 0.f) ? lg + log1pf(expf(-lg)) : log1pf(expf(lg));
            s += 2.0f * y * (sp - lg) + (1.0f - y) * sp;
        }
        red[tid] = s;
        __syncthreads();
        for (int st = 128; st; st >>= 1) {
            if (tid < st) red[tid] += red[tid + st];
            __syncthreads();
        }
        if (tid == 0) {
            float ca = c_attn[0], cp = c_pool[0];
            out[0] = red[0] / (float)Nn + ca * ca + cp * cp;
            g_ctr = 0;   // reset for next graph replay
        }
    }
}

static const int MMA_SMEM = 2 * 128 * SA * 2;              // 69632 (one A+B pair)
static const int K2_SMEM = MMA_SMEM + (8 * 128 + 3 * 128) * 4 + 128 * 4;
static const int K3B_SMEM = 2 * MMA_SMEM;                  // 139264 (double buffered)
static const int PREP_SMEM = KC * SST64 * 4 * 2;

extern "C" void kernel_launch(void* const* d_in, const int* in_sizes, int n_in,
                              void* d_out, int out_size) {
    const float* E       = (const float*)d_in[0];
    const float* Wq      = (const float*)d_in[1];
    const float* Wk      = (const float*)d_in[2];
    const float* Wv      = (const float*)d_in[3];
    const float* c_attn  = (const float*)d_in[4];
    const float* c_pool  = (const float*)d_in[5];
    const float* W1      = (const float*)d_in[6];
    const float* b1      = (const float*)d_in[7];
    const float* W2      = (const float*)d_in[8];
    const float* b2      = (const float*)d_in[9];
    const float* demo    = (const float*)d_in[10];
    const float* ht      = (const float*)d_in[11];
    const float* et      = (const float*)d_in[12];
    const float* labels  = (const float*)d_in[13];
    const int*   codes   = (const int*)d_in[14];
    const int*   lengths = (const int*)d_in[15];
    float* out = (float*)d_out;

    cudaFuncSetAttribute(k1x, cudaFuncAttributeMaxDynamicSharedMemorySize, MMA_SMEM);
    cudaFuncSetAttribute(k2_attn, cudaFuncAttributeMaxDynamicSharedMemorySize, K2_SMEM);
    cudaFuncSetAttribute(k3b_H, cudaFuncAttributeMaxDynamicSharedMemorySize, K3B_SMEM);

    k_prep<<<2691, 256, PREP_SMEM>>>(E, Wq, Wk, Wv, W1, demo, lengths);
    k1x<<<330, 256, MMA_SMEM>>>();
    k2_attn<<<Nn, 256, K2_SMEM>>>(codes, ht, et, lengths, c_attn, c_pool);
    k3b_H<<<dim3(16, 8), 256, K3B_SMEM>>>(b1, W2, labels, b2, c_attn, c_pool, out);
}

// round 12
// speedup vs baseline: 1.4865x; 1.4865x over previous
#include <cuda_runtime.h>
#include <cuda_bf16.h>
#include <math.h>

#define Vv 20000
#define Lh 128
#define Dd 256
#define DEMOd 70
#define HIDd 1024
#define Nn 2048
#define KC 32
#define SST64 68
#define SA 136     // bf16 operand panel stride (272B, 16B-aligned, conflict-free LDSM)
#define XK 384

typedef unsigned long long u64;
typedef unsigned int u32;

__device__ __forceinline__ u64 ffma2(u64 a, u64 b, u64 c) {
    u64 d; asm("fma.rn.f32x2 %0,%1,%2,%3;" : "=l"(d) : "l"(a), "l"(b), "l"(c)); return d;
}
__device__ __forceinline__ u64 splat2(float x) {
    u64 d; asm("mov.b64 %0,{%1,%1};" : "=l"(d) : "f"(x)); return d;
}
__device__ __forceinline__ u64 pk(float x, float y) {
    u64 d; asm("mov.b64 %0,{%1,%2};" : "=l"(d) : "f"(x), "f"(y)); return d;
}
__device__ __forceinline__ float2 unpk(u64 v) {
    float2 r; asm("mov.b64 {%0,%1},%2;" : "=f"(r.x), "=f"(r.y) : "l"(v)); return r;
}
__device__ __forceinline__ u32 pack_bf16(float lo, float hi) {
    u32 r; asm("cvt.rn.bf16x2.f32 %0, %1, %2;" : "=r"(r) : "f"(hi), "f"(lo)); return r;
}
__device__ __forceinline__ void mma_bf16(float* d, const u32* a, const u32* b) {
    asm volatile(
        "mma.sync.aligned.m16n8k16.row.col.f32.bf16.bf16.f32 "
        "{%0,%1,%2,%3},{%4,%5,%6,%7},{%8,%9},{%0,%1,%2,%3};"
        : "+f"(d[0]), "+f"(d[1]), "+f"(d[2]), "+f"(d[3])
        : "r"(a[0]), "r"(a[1]), "r"(a[2]), "r"(a[3]), "r"(b[0]), "r"(b[1]));
}
__device__ __forceinline__ void ldsm4(u32& r0, u32& r1, u32& r2, u32& r3, u32 a) {
    asm volatile("ldmatrix.sync.aligned.m8n8.x4.shared.b16 {%0,%1,%2,%3},[%4];"
                 : "=r"(r0), "=r"(r1), "=r"(r2), "=r"(r3) : "r"(a));
}
#define CP_ASYNC16(dst, src, sz) \
    asm volatile("cp.async.cg.shared.global [%0], [%1], 16, %2;" :: "r"(dst), "l"(src), "r"(sz))
#define CP_COMMIT() asm volatile("cp.async.commit_group;")
#define CP_WAIT0()  asm volatile("cp.async.wait_group 0;" ::: "memory")
#define CP_WAIT1()  asm volatile("cp.async.wait_group 1;" ::: "memory")

// ---------- device scratch ----------
__device__ __nv_bfloat16 g_E16[Vv * Dd];
__device__ __nv_bfloat16 g_EM16[Vv * Dd];
__device__ __nv_bfloat16 g_M16T[Dd * Dd];
__device__ __nv_bfloat16 g_Wv16[Dd * Dd];        // Wv straight bf16 [k][n]
__device__ __nv_bfloat16 g_W1rT[HIDd * Dd];      // W1[70:326]^T : [h][m]
__device__ __nv_bfloat16 g_WfT16[HIDd * XK];     // final combined weight^T [h][kk]
__device__ __nv_bfloat16 g_X16[Nn * XK];         // [demo | ebar | 0]
__device__ float g_part[Nn * 8];                 // partial logits
__device__ int g_perm[Nn];

__device__ __forceinline__ u32 a_lane_off(int lane, int warpRow) {
    return (u32)((warpRow + (lane & 15)) * SA + ((lane >> 4) << 3));
}
__device__ __forceinline__ u32 b_lane_off(int lane) {
    return (u32)(((lane & 7) + ((lane >> 4) << 3)) * SA + (((lane >> 3) & 1) << 3));
}

__device__ __forceinline__ void mma_ks_dense(u32 aAddr, u32 bAddr, float acc[16][4],
                                             int ks0, int ks1) {
    for (int ks = ks0; ks < ks1; ks++) {
        u32 a[4]; ldsm4(a[0], a[1], a[2], a[3], aAddr + ks * 32);
#pragma unroll
        for (int nt2 = 0; nt2 < 8; nt2++) {
            u32 b[4]; ldsm4(b[0], b[1], b[2], b[3], bAddr + nt2 * (16 * SA * 2) + ks * 32);
            mma_bf16(acc[2 * nt2], a, b);
            mma_bf16(acc[2 * nt2 + 1], a, b + 2);
        }
    }
}

// masked variant: STATIC unroll, predicated (keeps acc in registers)
__device__ __forceinline__ void mma_ks_masked(u32 aAddr, u32 bAddr, float acc[16][4],
                                              int ks0, int ks1, int nt2max, int len) {
    for (int ks = ks0; ks < ks1; ks++) {
        u32 a[4]; ldsm4(a[0], a[1], a[2], a[3], aAddr + ks * 32);
#pragma unroll
        for (int nt2 = 0; nt2 < 8; nt2++) {
            if (nt2 < nt2max) {
                u32 b[4];
                ldsm4(b[0], b[1], b[2], b[3], bAddr + nt2 * (16 * SA * 2) + ks * 32);
                mma_bf16(acc[2 * nt2], a, b);
                if (nt2 * 16 + 8 < len) mma_bf16(acc[2 * nt2 + 1], a, b + 2);
            }
        }
    }
}

// ============ merged prep kernel ============
// [0,16) k0_M | [16,1266) e16 x4 | [1266,1282) wv16 x4 | [1282,1666) w1T-split
// [1666,2690) x16 demo+zeros | 2690 sort
__global__ __launch_bounds__(256) void k_prep(
    const float* __restrict__ E, const float* __restrict__ Wq,
    const float* __restrict__ Wk, const float* __restrict__ Wv,
    const float* __restrict__ W1, const float* __restrict__ demo,
    const int* __restrict__ lengths) {
    extern __shared__ __align__(16) char psm[];
    int b = blockIdx.x, tid = threadIdx.x;

    if (b < 16) {                     // ---- M16T = (Wq Wk^T / 16)^T bf16
        float* As = (float*)psm;
        float* Bs = As + KC * SST64;
        int r0 = (b & 3) * 64, c0 = (b >> 2) * 64;
        int ty = tid >> 4, tx = tid & 15;
        int i0 = ty * 4, j0 = tx * 4;
        u64 acc[2][4];
#pragma unroll
        for (int a = 0; a < 2; a++)
#pragma unroll
            for (int c = 0; c < 4; c++) acc[a][c] = splat2(0.f);
        for (int k0 = 0; k0 < Dd; k0 += KC) {
            __syncthreads();
#pragma unroll
            for (int r = 0; r < 8; r++) {
                int idx = tid + r * 256;
                int i = idx >> 5, k = idx & 31;
                As[k * SST64 + i] = Wq[(r0 + i) * Dd + k0 + k];
                Bs[k * SST64 + i] = Wk[(c0 + i) * Dd + k0 + k];
            }
            __syncthreads();
#pragma unroll
            for (int k = 0; k < KC; k++) {
                float4 a0 = *(const float4*)(As + k * SST64 + i0);
                float4 b0 = *(const float4*)(Bs + k * SST64 + j0);
                u64 av[2] = {pk(a0.x, a0.y), pk(a0.z, a0.w)};
                float bv[4] = {b0.x, b0.y, b0.z, b0.w};
#pragma unroll
                for (int cc = 0; cc < 4; cc++) {
                    u64 bs = splat2(bv[cc]);
#pragma unroll
                    for (int a = 0; a < 2; a++) acc[a][cc] = ffma2(av[a], bs, acc[a][cc]);
                }
            }
        }
        const float sc = 1.0f / 16.0f;
#pragma unroll
        for (int a = 0; a < 2; a++)
#pragma unroll
            for (int c = 0; c < 4; c++) {
                float2 v = unpk(acc[a][c]);
                int row = r0 + i0 + 2 * a, col = c0 + j0 + c;
                g_M16T[col * Dd + row]     = __float2bfloat16(v.x * sc);
                g_M16T[col * Dd + row + 1] = __float2bfloat16(v.y * sc);
            }
    } else if (b < 1266) {            // ---- e16 (4 float4 per thread)
        int base = (b - 16) * 1024;
#pragma unroll
        for (int j = 0; j < 4; j++) {
            int idx = base + j * 256 + tid;
            float4 v = ((const float4*)E)[idx];
            uint2 o;
            o.x = pack_bf16(v.x, v.y);
            o.y = pack_bf16(v.z, v.w);
            ((uint2*)g_E16)[idx] = o;
        }
    } else if (b < 1282) {            // ---- Wv convert (4 float4 per thread)
        int base = (b - 1266) * 1024;
#pragma unroll
        for (int j = 0; j < 4; j++) {
            int idx = base + j * 256 + tid;
            float4 v = ((const float4*)Wv)[idx];
            uint2 o;
            o.x = pack_bf16(v.x, v.y);
            o.y = pack_bf16(v.z, v.w);
            ((uint2*)g_Wv16)[idx] = o;
        }
    } else if (b < 1666) {            // ---- W1^T split: demo cols -> WfT, repr rows -> W1rT
        float* t = (float*)psm;
        int local = b - 1282;
        int k0 = (local % 12) * 32, h0 = (local / 12) * 32;
        int tx = tid & 31, ty = tid >> 5;
#pragma unroll
        for (int i = 0; i < 4; i++) {
            int k = k0 + ty + i * 8;
            t[(ty + i * 8) * 33 + tx] = (k < DEMOd + Dd) ? W1[k * HIDd + h0 + tx] : 0.f;
        }
        __syncthreads();
#pragma unroll
        for (int i = 0; i < 4; i++) {
            int h = h0 + ty + i * 8;
            int kk = k0 + tx;
            float v = t[tx * 33 + ty + i * 8];
            if (kk < DEMOd)
                g_WfT16[h * XK + kk] = __float2bfloat16(v);
            else if (kk < DEMOd + Dd)
                g_W1rT[h * Dd + kk - DEMOd] = __float2bfloat16(v);
            else
                g_WfT16[h * XK + kk] = __float2bfloat16(0.f);
        }
    } else if (b < 2690) {            // ---- X16 demo cols + zero pad
        int local = b - 1666;
        int r = local * 2 + (tid >> 7);
        int t = tid & 127;
        if (t < DEMOd) g_X16[r * XK + t] = __float2bfloat16(demo[r * DEMOd + t]);
        else           g_X16[r * XK + 256 + t] = __float2bfloat16(0.f);   // 326..383
    } else {                          // ---- LPT sort
        __shared__ int hist[129], base[129];
        for (int c = tid; c < 129; c += 256) hist[c] = 0;
        __syncthreads();
        for (int i = tid; i < Nn; i += 256) atomicAdd(&hist[128 - lengths[i]], 1);
        __syncthreads();
        if (tid == 0) { int s = 0; for (int c = 0; c < 129; c++) { base[c] = s; s += hist[c]; } }
        __syncthreads();
        for (int i = tid; i < Nn; i += 256) {
            int pos = atomicAdd(&base[128 - lengths[i]], 1);
            g_perm[pos] = i;
        }
    }
}

// ---- K1x: blocks [0,314) EM GEMM, [314,330) Wcomb GEMM ----
__global__ __launch_bounds__(256, 2) void k1x() {
    extern __shared__ __align__(16) char smraw[];
    __nv_bfloat16* Asm = (__nv_bfloat16*)smraw;
    __nv_bfloat16* Bsm = Asm + 128 * SA;
    u32 smA = (u32)__cvta_generic_to_shared(Asm);
    u32 smB = (u32)__cvta_generic_to_shared(Bsm);

    int bx = blockIdx.x;
    int tid = threadIdx.x;
    int w = tid >> 5, lane = tid & 31;
    int g = lane >> 2, c4 = lane & 3;
    int warpRow = w * 16;
    u32 aAddr = smA + a_lane_off(lane, warpRow) * 2;
    u32 bAddr = smB + b_lane_off(lane) * 2;

    float acc[16][4];
#pragma unroll
    for (int t = 0; t < 16; t++)
        acc[t][0] = acc[t][1] = acc[t][2] = acc[t][3] = 0.f;

    if (bx < 314) {                   // ======== EM16 = E16 @ M ========
        int r0 = (bx % 157) * 128, c0 = (bx / 157) * 128;
        for (int p = 0; p < 2; p++) {
            __syncthreads();
#pragma unroll
            for (int half = 0; half < 2; half++) {
#pragma unroll
                for (int it = 0; it < 4; it++) {
                    int id = tid + it * 256;
                    int row = id >> 3, seg = (id & 7) + half * 8;
                    int ra = r0 + row;
                    const char* gA = (const char*)(g_E16 + (size_t)ra * Dd + p * 128) + seg * 16;
                    const char* gB = (const char*)(g_M16T + (size_t)(c0 + row) * Dd + p * 128) + seg * 16;
                    u32 off = (u32)(row * SA + seg * 8) * 2;
                    CP_ASYNC16(smA + off, gA, (ra < Vv) ? 16 : 0);
                    CP_ASYNC16(smB + off, gB, 16);
                }
                CP_COMMIT();
            }
            CP_WAIT1();
            __syncthreads();
            mma_ks_dense(aAddr, bAddr, acc, 0, 4);
            CP_WAIT0();
            __syncthreads();
            mma_ks_dense(aAddr, bAddr, acc, 4, 8);
        }
        int rr0 = r0 + warpRow + g, rr1 = rr0 + 8;
#pragma unroll
        for (int nt = 0; nt < 16; nt++) {
            int cc = c0 + nt * 8 + c4 * 2;
            if (rr0 < Vv)
                *(u32*)(g_EM16 + (size_t)rr0 * Dd + cc) = pack_bf16(acc[nt][0], acc[nt][1]);
            if (rr1 < Vv)
                *(u32*)(g_EM16 + (size_t)rr1 * Dd + cc) = pack_bf16(acc[nt][2], acc[nt][3]);
        }
    } else {                          // ======== WfT[:,70:326) = (Wv @ W1r)^T ========
        int bb = bx - 314;
        int h0 = (bb & 7) * 128, k0 = (bb >> 3) * 128;
        for (int p = 0; p < 2; p++) {
            __syncthreads();
#pragma unroll
            for (int it = 0; it < 8; it++) {
                int id = tid + it * 256;
                int row = id >> 4, seg = id & 15;
                const char* gA = (const char*)(g_W1rT + (size_t)(h0 + row) * Dd + p * 128) + seg * 16;
                const char* gB = (const char*)(g_Wv16 + (size_t)(k0 + row) * Dd + p * 128) + seg * 16;
                CP_ASYNC16(smA + (row * SA + seg * 8) * 2, gA, 16);
                CP_ASYNC16(smB + (row * SA + seg * 8) * 2, gB, 16);
            }
            CP_COMMIT(); CP_WAIT0();
            __syncthreads();
            mma_ks_dense(aAddr, bAddr, acc, 0, 8);
        }
        int rr0 = h0 + warpRow + g, rr1 = rr0 + 8;
#pragma unroll
        for (int nt = 0; nt < 16; nt++) {
            int cc = DEMOd + k0 + nt * 8 + c4 * 2;
            *(u32*)(g_WfT16 + (size_t)rr0 * XK + cc) = pack_bf16(acc[nt][0], acc[nt][1]);
            *(u32*)(g_WfT16 + (size_t)rr1 * XK + cc) = pack_bf16(acc[nt][2], acc[nt][3]);
        }
    }
}

// ---- K2: per-sample attention + pooling -> X16[:,70:326).  grid 2048 ----
__global__ __launch_bounds__(256, 2) void k2_attn(
    const int* __restrict__ codes,
    const float* __restrict__ ht, const float* __restrict__ et,
    const int* __restrict__ lengths, const float* __restrict__ c_attn,
    const float* __restrict__ c_pool) {
    extern __shared__ __align__(16) char smraw[];
    __nv_bfloat16* Asm = (__nv_bfloat16*)smraw;
    __nv_bfloat16* Bsm = Asm + 128 * SA;
    float* cs = (float*)(Bsm + 128 * SA);
    float* wv = cs + 8 * 128;
    float* pv = wv + 128;
    float* tv = pv + 128;
    int*   cd = (int*)(tv + 128);
    u32 smA = (u32)__cvta_generic_to_shared(Asm);
    u32 smB = (u32)__cvta_generic_to_shared(Bsm);

    int n = g_perm[blockIdx.x];
    int tid = threadIdx.x;
    int len = lengths[n];
    int w = tid >> 5, lane = tid & 31;
    int g = lane >> 2, c4 = lane & 3;

    if (tid < 128) {
        cd[tid] = codes[n * Lh + tid];
        tv[tid] = ht[n * Lh + tid];
        wv[tid] = 0.f;
    }
    __syncthreads();

    if (tid < 32) {
        float cp = c_pool[0], e_t = et[n];
        float ssum = 0.f;
        for (int i = tid; i < len; i += 32) {
            float e = __expf(-cp * (e_t - tv[i]));
            wv[i] = e; ssum += e;
        }
#pragma unroll
        for (int o = 16; o; o >>= 1) ssum += __shfl_xor_sync(~0u, ssum, o);
        float inv = 1.f / ssum;
        for (int i = tid; i < len; i += 32) wv[i] *= inv;
    }

    int warpRow = w * 16;
    bool wact = warpRow < len;
    int lim = (len + 15) & ~15;
    int nt2max = (len + 15) >> 4;
    u32 aAddr = smA + a_lane_off(lane, warpRow) * 2;
    u32 bAddr = smB + b_lane_off(lane) * 2;

    float acc[16][4];
#pragma unroll
    for (int t = 0; t < 16; t++)
        acc[t][0] = acc[t][1] = acc[t][2] = acc[t][3] = 0.f;

    for (int p = 0; p < 2; p++) {
        __syncthreads();
#pragma unroll
        for (int half = 0; half < 2; half++) {
#pragma unroll
            for (int it = 0; it < 4; it++) {
                int id = tid + it * 256;
                int row = id >> 3, seg = (id & 7) + half * 8;
                if (row < lim) {
                    int c = cd[row];
                    const char* gA = (const char*)(g_EM16 + (size_t)c * Dd + p * 128) + seg * 16;
                    const char* gB = (const char*)(g_E16 + (size_t)c * Dd + p * 128) + seg * 16;
                    u32 off = (u32)(row * SA + seg * 8) * 2;
                    int sz = (row < len) ? 16 : 0;
                    CP_ASYNC16(smA + off, gA, sz);
                    CP_ASYNC16(smB + off, gB, sz);
                }
            }
            CP_COMMIT();
        }
        CP_WAIT1();
        __syncthreads();
        if (wact) mma_ks_masked(aAddr, bAddr, acc, 0, 4, nt2max, len);
        CP_WAIT0();
        __syncthreads();
        if (wact) mma_ks_masked(aAddr, bAddr, acc, 4, 8, nt2max, len);
    }

    // reload E16 k-half0 into Asm, overlapped with the softmax below
    __syncthreads();
#pragma unroll
    for (int it = 0; it < 8; it++) {
        int id = tid + it * 256;
        int row = id >> 4, seg = id & 15;
        if (row < lim) {
            int c = cd[row];
            const char* gB = (const char*)(g_E16 + (size_t)c * Dd) + seg * 16;
            int sz = (row < len) ? 16 : 0;
            CP_ASYNC16(smA + (u32)(row * SA + seg * 8) * 2, gB, sz);
        }
    }
    CP_COMMIT();

    float sc0 = 0.f, sc1 = 0.f;
    if (wact) {
        float ca = c_attn[0];
        int r0 = warpRow + g, r1 = r0 + 8;
        float ti0 = tv[r0], ti1 = tv[r1];
        float s0 = 0.f, s1 = 0.f;
#pragma unroll
        for (int nt = 0; nt < 16; nt++) {
            int j0 = nt * 8 + c4 * 2;
            if (nt * 8 < len) {
                float tj0 = tv[j0], tj1 = tv[j0 + 1];
                float e00 = (j0     < len) ? __expf(acc[nt][0] - ca * fabsf(ti0 - tj0)) : 0.f;
                float e01 = (j0 + 1 < len) ? __expf(acc[nt][1] - ca * fabsf(ti0 - tj1)) : 0.f;
                float e10 = (j0     < len) ? __expf(acc[nt][2] - ca * fabsf(ti1 - tj0)) : 0.f;
                float e11 = (j0 + 1 < len) ? __expf(acc[nt][3] - ca * fabsf(ti1 - tj1)) : 0.f;
                acc[nt][0] = e00; acc[nt][1] = e01; acc[nt][2] = e10; acc[nt][3] = e11;
                s0 += e00 + e01; s1 += e10 + e11;
            }
        }
        s0 += __shfl_xor_sync(~0u, s0, 1); s0 += __shfl_xor_sync(~0u, s0, 2);
        s1 += __shfl_xor_sync(~0u, s1, 1); s1 += __shfl_xor_sync(~0u, s1, 2);
        sc0 = wv[r0] / s0;
        sc1 = wv[r1] / s1;
    }

#pragma unroll
    for (int nt = 0; nt < 16; nt++) {
        float v0 = 0.f, v1 = 0.f;
        if (wact && nt * 8 < len) {
            v0 = acc[nt][0] * sc0 + acc[nt][2] * sc1;
            v1 = acc[nt][1] * sc0 + acc[nt][3] * sc1;
        }
        v0 += __shfl_xor_sync(~0u, v0, 4);  v1 += __shfl_xor_sync(~0u, v1, 4);
        v0 += __shfl_xor_sync(~0u, v0, 8);  v1 += __shfl_xor_sync(~0u, v1, 8);
        v0 += __shfl_xor_sync(~0u, v0, 16); v1 += __shfl_xor_sync(~0u, v1, 16);
        if (g == 0) {
            int j0 = nt * 8 + c4 * 2;
            cs[w * 128 + j0] = v0;
            cs[w * 128 + j0 + 1] = v1;
        }
    }
    __syncthreads();
    if (tid < 128) {
        float p = 0.f;
#pragma unroll
        for (int q = 0; q < 8; q++) p += cs[q * 128 + tid];
        pv[tid] = p;
    }
    CP_WAIT0();
    __syncthreads();

    // ebar_d -> X16[n][70 + d]
    const __nv_bfloat16* base = (tid < 128) ? (Asm + tid) : (Bsm + (tid - 128));
    float a = 0.f;
#pragma unroll 4
    for (int j = 0; j < len; j++)
        a = fmaf(pv[j], __bfloat162float(base[j * SA]), a);
    g_X16[(size_t)n * XK + DEMOd + tid] = __float2bfloat16(a);
}

// ---- K3b: partial logits = relu(X @ Wf + b1) . W2, per 128-col chunk.  grid (16,8) ----
__global__ __launch_bounds__(256, 2) void k3b_H(const float* __restrict__ b1,
                                                const float* __restrict__ W2) {
    extern __shared__ __align__(16) char smraw[];
    __nv_bfloat16* Asm = (__nv_bfloat16*)smraw;
    __nv_bfloat16* Bsm = Asm + 128 * SA;
    u32 smA = (u32)__cvta_generic_to_shared(Asm);
    u32 smB = (u32)__cvta_generic_to_shared(Bsm);

    int r0 = blockIdx.x * 128, c0 = blockIdx.y * 128;
    int tid = threadIdx.x;
    int w = tid >> 5, lane = tid & 31;
    int g = lane >> 2, c4 = lane & 3;
    int warpRow = w * 16;
    u32 aAddr = smA + a_lane_off(lane, warpRow) * 2;
    u32 bAddr = smB + b_lane_off(lane) * 2;

    float acc[16][4];
#pragma unroll
    for (int t = 0; t < 16; t++)
        acc[t][0] = acc[t][1] = acc[t][2] = acc[t][3] = 0.f;

    for (int p = 0; p < 3; p++) {
        __syncthreads();
#pragma unroll
        for (int it = 0; it < 8; it++) {
            int id = tid + it * 256;
            int row = id >> 4, seg = id & 15;
            const char* gA = (const char*)(g_X16 + (size_t)(r0 + row) * XK + p * 128) + seg * 16;
            const char* gB = (const char*)(g_WfT16 + (size_t)(c0 + row) * XK + p * 128) + seg * 16;
            CP_ASYNC16(smA + (row * SA + seg * 8) * 2, gA, 16);
            CP_ASYNC16(smB + (row * SA + seg * 8) * 2, gB, 16);
        }
        CP_COMMIT(); CP_WAIT0();
        __syncthreads();
        mma_ks_dense(aAddr, bAddr, acc, 0, 8);
    }
    int rr0 = r0 + warpRow + g, rr1 = rr0 + 8;
    float p0 = 0.f, p1 = 0.f;
#pragma unroll
    for (int nt = 0; nt < 16; nt++) {
        int col = c0 + nt * 8 + c4 * 2;
        float bb0 = b1[col], bb1 = b1[col + 1];
        float w0 = W2[col], w1 = W2[col + 1];
        p0 += fmaxf(acc[nt][0] + bb0, 0.f) * w0 + fmaxf(acc[nt][1] + bb1, 0.f) * w1;
        p1 += fmaxf(acc[nt][2] + bb0, 0.f) * w0 + fmaxf(acc[nt][3] + bb1, 0.f) * w1;
    }
    p0 += __shfl_xor_sync(~0u, p0, 1); p0 += __shfl_xor_sync(~0u, p0, 2);
    p1 += __shfl_xor_sync(~0u, p1, 1); p1 += __shfl_xor_sync(~0u, p1, 2);
    if (c4 == 0) {
        g_part[rr0 * 8 + blockIdx.y] = p0;
        g_part[rr1 * 8 + blockIdx.y] = p1;
    }
}

// ---- K4: logits -> BCE -> deterministic mean + reg ----
__global__ __launch_bounds__(256) void k4_final(const float* __restrict__ labels,
                                                const float* __restrict__ b2,
                                                const float* __restrict__ c_attn,
                                                const float* __restrict__ c_pool,
                                                float* __restrict__ out) {
    __shared__ float red[256];
    int tid = threadIdx.x;
    float s = 0.f;
    for (int i = tid; i < Nn; i += 256) {
        float lg = b2[0];
#pragma unroll
        for (int q = 0; q < 8; q++) lg += g_part[i * 8 + q];
        float y = labels[i];
        float sp = (lg > 0.f) ? lg + log1pf(expf(-lg)) : log1pf(expf(lg));
        s += 2.0f * y * (sp - lg) + (1.0f - y) * sp;
    }
    red[tid] = s;
    __syncthreads();
    for (int st = 128; st; st >>= 1) {
        if (tid < st) red[tid] += red[tid + st];
        __syncthreads();
    }
    if (tid == 0) {
        float ca = c_attn[0], cp = c_pool[0];
        out[0] = red[0] / (float)Nn + ca * ca + cp * cp;
    }
}

static const int MMA_SMEM = 2 * 128 * SA * 2;
static const int K2_SMEM = MMA_SMEM + (8 * 128 + 3 * 128) * 4 + 128 * 4;
static const int PREP_SMEM = KC * SST64 * 4 * 2;

extern "C" void kernel_launch(void* const* d_in, const int* in_sizes, int n_in,
                              void* d_out, int out_size) {
    const float* E       = (const float*)d_in[0];
    const float* Wq      = (const float*)d_in[1];
    const float* Wk      = (const float*)d_in[2];
    const float* Wv      = (const float*)d_in[3];
    const float* c_attn  = (const float*)d_in[4];
    const float* c_pool  = (const float*)d_in[5];
    const float* W1      = (const float*)d_in[6];
    const float* b1      = (const float*)d_in[7];
    const float* W2      = (const float*)d_in[8];
    const float* b2      = (const float*)d_in[9];
    const float* demo    = (const float*)d_in[10];
    const float* ht      = (const float*)d_in[11];
    const float* et      = (const float*)d_in[12];
    const float* labels  = (const float*)d_in[13];
    const int*   codes   = (const int*)d_in[14];
    const int*   lengths = (const int*)d_in[15];
    float* out = (float*)d_out;

    cudaFuncSetAttribute(k1x, cudaFuncAttributeMaxDynamicSharedMemorySize, MMA_SMEM);
    cudaFuncSetAttribute(k2_attn, cudaFuncAttributeMaxDynamicSharedMemorySize, K2_SMEM);
    cudaFuncSetAttribute(k3b_H, cudaFuncAttributeMaxDynamicSharedMemorySize, MMA_SMEM);

    k_prep<<<2691, 256, PREP_SMEM>>>(E, Wq, Wk, Wv, W1, demo, lengths);
    k1x<<<330, 256, MMA_SMEM>>>();
    k2_attn<<<Nn, 256, K2_SMEM>>>(codes, ht, et, lengths, c_attn, c_pool);
    k3b_H<<<dim3(16, 8), 256, MMA_SMEM>>>(b1, W2);
    k4_final<<<1, 256>>>(labels, b2, c_attn, c_pool, out);
}

// round 14
// speedup vs baseline: 1.5143x; 1.0187x over previous
#include <cuda_runtime.h>
#include <cuda_bf16.h>
#include <math.h>

#define Vv 20000
#define Lh 128
#define Dd 256
#define DEMOd 70
#define HIDd 1024
#define Nn 2048
#define KC 32
#define SST64 68
#define SA 136     // bf16 operand panel stride (272B, 16B-aligned, conflict-free LDSM)
#define XK 384

typedef unsigned long long u64;
typedef unsigned int u32;

__device__ __forceinline__ u64 ffma2(u64 a, u64 b, u64 c) {
    u64 d; asm("fma.rn.f32x2 %0,%1,%2,%3;" : "=l"(d) : "l"(a), "l"(b), "l"(c)); return d;
}
__device__ __forceinline__ u64 splat2(float x) {
    u64 d; asm("mov.b64 %0,{%1,%1};" : "=l"(d) : "f"(x)); return d;
}
__device__ __forceinline__ u64 pk(float x, float y) {
    u64 d; asm("mov.b64 %0,{%1,%2};" : "=l"(d) : "f"(x), "f"(y)); return d;
}
__device__ __forceinline__ float2 unpk(u64 v) {
    float2 r; asm("mov.b64 {%0,%1},%2;" : "=f"(r.x), "=f"(r.y) : "l"(v)); return r;
}
__device__ __forceinline__ u32 pack_bf16(float lo, float hi) {
    u32 r; asm("cvt.rn.bf16x2.f32 %0, %1, %2;" : "=r"(r) : "f"(hi), "f"(lo)); return r;
}
__device__ __forceinline__ void mma_bf16(float* d, const u32* a, const u32* b) {
    asm volatile(
        "mma.sync.aligned.m16n8k16.row.col.f32.bf16.bf16.f32 "
        "{%0,%1,%2,%3},{%4,%5,%6,%7},{%8,%9},{%0,%1,%2,%3};"
        : "+f"(d[0]), "+f"(d[1]), "+f"(d[2]), "+f"(d[3])
        : "r"(a[0]), "r"(a[1]), "r"(a[2]), "r"(a[3]), "r"(b[0]), "r"(b[1]));
}
__device__ __forceinline__ void ldsm4(u32& r0, u32& r1, u32& r2, u32& r3, u32 a) {
    asm volatile("ldmatrix.sync.aligned.m8n8.x4.shared.b16 {%0,%1,%2,%3},[%4];"
                 : "=r"(r0), "=r"(r1), "=r"(r2), "=r"(r3) : "r"(a));
}
#define CP_ASYNC16(dst, src, sz) \
    asm volatile("cp.async.cg.shared.global [%0], [%1], 16, %2;" :: "r"(dst), "l"(src), "r"(sz))
#define CP_COMMIT() asm volatile("cp.async.commit_group;")
#define CP_WAIT0()  asm volatile("cp.async.wait_group 0;" ::: "memory")
#define CP_WAIT1()  asm volatile("cp.async.wait_group 1;" ::: "memory")

// ---------- device scratch ----------
__device__ __nv_bfloat16 g_E16[Vv * Dd];
__device__ __nv_bfloat16 g_EM16[Vv * Dd];
__device__ __nv_bfloat16 g_M16T[Dd * Dd];
__device__ __nv_bfloat16 g_Wv16[Dd * Dd];        // Wv straight bf16 [k][n]
__device__ __nv_bfloat16 g_W1rT[HIDd * Dd];      // W1[70:326]^T : [h][m]
__device__ __nv_bfloat16 g_WfT16[HIDd * XK];     // final combined weight^T [h][kk]
__device__ __nv_bfloat16 g_X16[Nn * XK];         // [demo | ebar | 0]
__device__ float g_part[Nn * 8];                 // partial logits
__device__ int g_perm[Nn];

__device__ __forceinline__ u32 a_lane_off(int lane, int warpRow) {
    return (u32)((warpRow + (lane & 15)) * SA + ((lane >> 4) << 3));
}
__device__ __forceinline__ u32 b_lane_off(int lane) {
    return (u32)(((lane & 7) + ((lane >> 4) << 3)) * SA + (((lane >> 3) & 1) << 3));
}

__device__ __forceinline__ void mma_ks_dense(u32 aAddr, u32 bAddr, float acc[16][4],
                                             int ks0, int ks1) {
    for (int ks = ks0; ks < ks1; ks++) {
        u32 a[4]; ldsm4(a[0], a[1], a[2], a[3], aAddr + ks * 32);
#pragma unroll
        for (int nt2 = 0; nt2 < 8; nt2++) {
            u32 b[4]; ldsm4(b[0], b[1], b[2], b[3], bAddr + nt2 * (16 * SA * 2) + ks * 32);
            mma_bf16(acc[2 * nt2], a, b);
            mma_bf16(acc[2 * nt2 + 1], a, b + 2);
        }
    }
}

// masked variant: STATIC unroll, predicated (keeps acc in registers)
__device__ __forceinline__ void mma_ks_masked(u32 aAddr, u32 bAddr, float acc[16][4],
                                              int ks0, int ks1, int nt2max, int len) {
    for (int ks = ks0; ks < ks1; ks++) {
        u32 a[4]; ldsm4(a[0], a[1], a[2], a[3], aAddr + ks * 32);
#pragma unroll
        for (int nt2 = 0; nt2 < 8; nt2++) {
            if (nt2 < nt2max) {
                u32 b[4];
                ldsm4(b[0], b[1], b[2], b[3], bAddr + nt2 * (16 * SA * 2) + ks * 32);
                mma_bf16(acc[2 * nt2], a, b);
                if (nt2 * 16 + 8 < len) mma_bf16(acc[2 * nt2 + 1], a, b + 2);
            }
        }
    }
}

// ---- dummy: shifts capture slot so k2 is the 4th launch ----
__global__ void k_dummy() {}

// ============ merged prep kernel ============
// [0,16) k0_M | [16,1266) e16 x4 | [1266,1282) wv16 x4 | [1282,1666) w1T-split
// [1666,2690) x16 demo+zeros | 2690 sort
__global__ __launch_bounds__(256) void k_prep(
    const float* __restrict__ E, const float* __restrict__ Wq,
    const float* __restrict__ Wk, const float* __restrict__ Wv,
    const float* __restrict__ W1, const float* __restrict__ demo,
    const int* __restrict__ lengths) {
    extern __shared__ __align__(16) char psm[];
    int b = blockIdx.x, tid = threadIdx.x;

    if (b < 16) {                     // ---- M16T = (Wq Wk^T / 16)^T bf16
        float* As = (float*)psm;
        float* Bs = As + KC * SST64;
        int r0 = (b & 3) * 64, c0 = (b >> 2) * 64;
        int ty = tid >> 4, tx = tid & 15;
        int i0 = ty * 4, j0 = tx * 4;
        u64 acc[2][4];
#pragma unroll
        for (int a = 0; a < 2; a++)
#pragma unroll
            for (int c = 0; c < 4; c++) acc[a][c] = splat2(0.f);
        for (int k0 = 0; k0 < Dd; k0 += KC) {
            __syncthreads();
#pragma unroll
            for (int r = 0; r < 8; r++) {
                int idx = tid + r * 256;
                int i = idx >> 5, k = idx & 31;
                As[k * SST64 + i] = Wq[(r0 + i) * Dd + k0 + k];
                Bs[k * SST64 + i] = Wk[(c0 + i) * Dd + k0 + k];
            }
            __syncthreads();
#pragma unroll
            for (int k = 0; k < KC; k++) {
                float4 a0 = *(const float4*)(As + k * SST64 + i0);
                float4 b0 = *(const float4*)(Bs + k * SST64 + j0);
                u64 av[2] = {pk(a0.x, a0.y), pk(a0.z, a0.w)};
                float bv[4] = {b0.x, b0.y, b0.z, b0.w};
#pragma unroll
                for (int cc = 0; cc < 4; cc++) {
                    u64 bs = splat2(bv[cc]);
#pragma unroll
                    for (int a = 0; a < 2; a++) acc[a][cc] = ffma2(av[a], bs, acc[a][cc]);
                }
            }
        }
        const float sc = 1.0f / 16.0f;
#pragma unroll
        for (int a = 0; a < 2; a++)
#pragma unroll
            for (int c = 0; c < 4; c++) {
                float2 v = unpk(acc[a][c]);
                int row = r0 + i0 + 2 * a, col = c0 + j0 + c;
                g_M16T[col * Dd + row]     = __float2bfloat16(v.x * sc);
                g_M16T[col * Dd + row + 1] = __float2bfloat16(v.y * sc);
            }
    } else if (b < 1266) {            // ---- e16 (4 float4 per thread)
        int base = (b - 16) * 1024;
#pragma unroll
        for (int j = 0; j < 4; j++) {
            int idx = base + j * 256 + tid;
            float4 v = ((const float4*)E)[idx];
            uint2 o;
            o.x = pack_bf16(v.x, v.y);
            o.y = pack_bf16(v.z, v.w);
            ((uint2*)g_E16)[idx] = o;
        }
    } else if (b < 1282) {            // ---- Wv convert (4 float4 per thread)
        int base = (b - 1266) * 1024;
#pragma unroll
        for (int j = 0; j < 4; j++) {
            int idx = base + j * 256 + tid;
            float4 v = ((const float4*)Wv)[idx];
            uint2 o;
            o.x = pack_bf16(v.x, v.y);
            o.y = pack_bf16(v.z, v.w);
            ((uint2*)g_Wv16)[idx] = o;
        }
    } else if (b < 1666) {            // ---- W1^T split: demo cols -> WfT, repr rows -> W1rT
        float* t = (float*)psm;
        int local = b - 1282;
        int k0 = (local % 12) * 32, h0 = (local / 12) * 32;
        int tx = tid & 31, ty = tid >> 5;
#pragma unroll
        for (int i = 0; i < 4; i++) {
            int k = k0 + ty + i * 8;
            t[(ty + i * 8) * 33 + tx] = (k < DEMOd + Dd) ? W1[k * HIDd + h0 + tx] : 0.f;
        }
        __syncthreads();
#pragma unroll
        for (int i = 0; i < 4; i++) {
            int h = h0 + ty + i * 8;
            int kk = k0 + tx;
            float v = t[tx * 33 + ty + i * 8];
            if (kk < DEMOd)
                g_WfT16[h * XK + kk] = __float2bfloat16(v);
            else if (kk < DEMOd + Dd)
                g_W1rT[h * Dd + kk - DEMOd] = __float2bfloat16(v);
            else
                g_WfT16[h * XK + kk] = __float2bfloat16(0.f);
        }
    } else if (b < 2690) {            // ---- X16 demo cols + zero pad
        int local = b - 1666;
        int r = local * 2 + (tid >> 7);
        int t = tid & 127;
        if (t < DEMOd) g_X16[r * XK + t] = __float2bfloat16(demo[r * DEMOd + t]);
        else           g_X16[r * XK + 256 + t] = __float2bfloat16(0.f);   // 326..383
    } else {                          // ---- LPT sort
        __shared__ int hist[129], base[129];
        for (int c = tid; c < 129; c += 256) hist[c] = 0;
        __syncthreads();
        for (int i = tid; i < Nn; i += 256) atomicAdd(&hist[128 - lengths[i]], 1);
        __syncthreads();
        if (tid == 0) { int s = 0; for (int c = 0; c < 129; c++) { base[c] = s; s += hist[c]; } }
        __syncthreads();
        for (int i = tid; i < Nn; i += 256) {
            int pos = atomicAdd(&base[128 - lengths[i]], 1);
            g_perm[pos] = i;
        }
    }
}

// ---- K1x: blocks [0,314) EM GEMM, [314,330) Wcomb GEMM ----
__global__ __launch_bounds__(256, 2) void k1x() {
    extern __shared__ __align__(16) char smraw[];
    __nv_bfloat16* Asm = (__nv_bfloat16*)smraw;
    __nv_bfloat16* Bsm = Asm + 128 * SA;
    u32 smA = (u32)__cvta_generic_to_shared(Asm);
    u32 smB = (u32)__cvta_generic_to_shared(Bsm);

    int bx = blockIdx.x;
    int tid = threadIdx.x;
    int w = tid >> 5, lane = tid & 31;
    int g = lane >> 2, c4 = lane & 3;
    int warpRow = w * 16;
    u32 aAddr = smA + a_lane_off(lane, warpRow) * 2;
    u32 bAddr = smB + b_lane_off(lane) * 2;

    float acc[16][4];
#pragma unroll
    for (int t = 0; t < 16; t++)
        acc[t][0] = acc[t][1] = acc[t][2] = acc[t][3] = 0.f;

    if (bx < 314) {                   // ======== EM16 = E16 @ M ========
        int r0 = (bx % 157) * 128, c0 = (bx / 157) * 128;
        for (int p = 0; p < 2; p++) {
            __syncthreads();
#pragma unroll
            for (int half = 0; half < 2; half++) {
#pragma unroll
                for (int it = 0; it < 4; it++) {
                    int id = tid + it * 256;
                    int row = id >> 3, seg = (id & 7) + half * 8;
                    int ra = r0 + row;
                    const char* gA = (const char*)(g_E16 + (size_t)ra * Dd + p * 128) + seg * 16;
                    const char* gB = (const char*)(g_M16T + (size_t)(c0 + row) * Dd + p * 128) + seg * 16;
                    u32 off = (u32)(row * SA + seg * 8) * 2;
                    CP_ASYNC16(smA + off, gA, (ra < Vv) ? 16 : 0);
                    CP_ASYNC16(smB + off, gB, 16);
                }
                CP_COMMIT();
            }
            CP_WAIT1();
            __syncthreads();
            mma_ks_dense(aAddr, bAddr, acc, 0, 4);
            CP_WAIT0();
            __syncthreads();
            mma_ks_dense(aAddr, bAddr, acc, 4, 8);
        }
        int rr0 = r0 + warpRow + g, rr1 = rr0 + 8;
#pragma unroll
        for (int nt = 0; nt < 16; nt++) {
            int cc = c0 + nt * 8 + c4 * 2;
            if (rr0 < Vv)
                *(u32*)(g_EM16 + (size_t)rr0 * Dd + cc) = pack_bf16(acc[nt][0], acc[nt][1]);
            if (rr1 < Vv)
                *(u32*)(g_EM16 + (size_t)rr1 * Dd + cc) = pack_bf16(acc[nt][2], acc[nt][3]);
        }
    } else {                          // ======== WfT[:,70:326) = (Wv @ W1r)^T ========
        int bb = bx - 314;
        int h0 = (bb & 7) * 128, k0 = (bb >> 3) * 128;
        for (int p = 0; p < 2; p++) {
            __syncthreads();
#pragma unroll
            for (int it = 0; it < 8; it++) {
                int id = tid + it * 256;
                int row = id >> 4, seg = id & 15;
                const char* gA = (const char*)(g_W1rT + (size_t)(h0 + row) * Dd + p * 128) + seg * 16;
                const char* gB = (const char*)(g_Wv16 + (size_t)(k0 + row) * Dd + p * 128) + seg * 16;
                CP_ASYNC16(smA + (row * SA + seg * 8) * 2, gA, 16);
                CP_ASYNC16(smB + (row * SA + seg * 8) * 2, gB, 16);
            }
            CP_COMMIT(); CP_WAIT0();
            __syncthreads();
            mma_ks_dense(aAddr, bAddr, acc, 0, 8);
        }
        int rr0 = h0 + warpRow + g, rr1 = rr0 + 8;
#pragma unroll
        for (int nt = 0; nt < 16; nt++) {
            int cc = DEMOd + k0 + nt * 8 + c4 * 2;
            *(u32*)(g_WfT16 + (size_t)rr0 * XK + cc) = pack_bf16(acc[nt][0], acc[nt][1]);
            *(u32*)(g_WfT16 + (size_t)rr1 * XK + cc) = pack_bf16(acc[nt][2], acc[nt][3]);
        }
    }
}

// ---- K2: per-sample attention + pooling -> X16[:,70:326).  grid 2048 ----
__global__ __launch_bounds__(256, 2) void k2_attn(
    const int* __restrict__ codes,
    const float* __restrict__ ht, const float* __restrict__ et,
    const int* __restrict__ lengths, const float* __restrict__ c_attn,
    const float* __restrict__ c_pool) {
    extern __shared__ __align__(16) char smraw[];
    __nv_bfloat16* Asm = (__nv_bfloat16*)smraw;
    __nv_bfloat16* Bsm = Asm + 128 * SA;
    float* cs = (float*)(Bsm + 128 * SA);
    float* wv = cs + 8 * 128;
    float* pv = wv + 128;
    float* tv = pv + 128;
    int*   cd = (int*)(tv + 128);
    u32 smA = (u32)__cvta_generic_to_shared(Asm);
    u32 smB = (u32)__cvta_generic_to_shared(Bsm);

    int n = g_perm[blockIdx.x];
    int tid = threadIdx.x;
    int len = lengths[n];
    int w = tid >> 5, lane = tid & 31;
    int g = lane >> 2, c4 = lane & 3;

    if (tid < 128) {
        cd[tid] = codes[n * Lh + tid];
        tv[tid] = ht[n * Lh + tid];
        wv[tid] = 0.f;
    }
    __syncthreads();

    if (tid < 32) {
        float cp = c_pool[0], e_t = et[n];
        float ssum = 0.f;
        for (int i = tid; i < len; i += 32) {
            float e = __expf(-cp * (e_t - tv[i]));
            wv[i] = e; ssum += e;
        }
#pragma unroll
        for (int o = 16; o; o >>= 1) ssum += __shfl_xor_sync(~0u, ssum, o);
        float inv = 1.f / ssum;
        for (int i = tid; i < len; i += 32) wv[i] *= inv;
    }

    int warpRow = w * 16;
    bool wact = warpRow < len;
    int lim = (len + 15) & ~15;
    int nt2max = (len + 15) >> 4;
    u32 aAddr = smA + a_lane_off(lane, warpRow) * 2;
    u32 bAddr = smB + b_lane_off(lane) * 2;

    float acc[16][4];
#pragma unroll
    for (int t = 0; t < 16; t++)
        acc[t][0] = acc[t][1] = acc[t][2] = acc[t][3] = 0.f;

    for (int p = 0; p < 2; p++) {
        __syncthreads();
#pragma unroll
        for (int half = 0; half < 2; half++) {
#pragma unroll
            for (int it = 0; it < 4; it++) {
                int id = tid + it * 256;
                int row = id >> 3, seg = (id & 7) + half * 8;
                if (row < lim) {
                    int c = cd[row];
                    const char* gA = (const char*)(g_EM16 + (size_t)c * Dd + p * 128) + seg * 16;
                    const char* gB = (const char*)(g_E16 + (size_t)c * Dd + p * 128) + seg * 16;
                    u32 off = (u32)(row * SA + seg * 8) * 2;
                    int sz = (row < len) ? 16 : 0;
                    CP_ASYNC16(smA + off, gA, sz);
                    CP_ASYNC16(smB + off, gB, sz);
                }
            }
            CP_COMMIT();
        }
        CP_WAIT1();
        __syncthreads();
        if (wact) mma_ks_masked(aAddr, bAddr, acc, 0, 4, nt2max, len);
        CP_WAIT0();
        __syncthreads();
        if (wact) mma_ks_masked(aAddr, bAddr, acc, 4, 8, nt2max, len);
    }

    // reload E16 k-half0 into Asm, overlapped with the softmax below
    // (only rows < len: rows in [len, lim) are never read by the ebar loop)
    __syncthreads();
#pragma unroll
    for (int it = 0; it < 8; it++) {
        int id = tid + it * 256;
        int row = id >> 4, seg = id & 15;
        if (row < len) {
            int c = cd[row];
            const char* gB = (const char*)(g_E16 + (size_t)c * Dd) + seg * 16;
            CP_ASYNC16(smA + (u32)(row * SA + seg * 8) * 2, gB, 16);
        }
    }
    CP_COMMIT();

    float sc0 = 0.f, sc1 = 0.f;
    if (wact) {
        float ca = c_attn[0];
        int r0 = warpRow + g, r1 = r0 + 8;
        float ti0 = tv[r0], ti1 = tv[r1];
        float s0 = 0.f, s1 = 0.f;
#pragma unroll
        for (int nt = 0; nt < 16; nt++) {
            int j0 = nt * 8 + c4 * 2;
            if (nt * 8 < len) {
                float tj0 = tv[j0], tj1 = tv[j0 + 1];
                float e00 = (j0     < len) ? __expf(acc[nt][0] - ca * fabsf(ti0 - tj0)) : 0.f;
                float e01 = (j0 + 1 < len) ? __expf(acc[nt][1] - ca * fabsf(ti0 - tj1)) : 0.f;
                float e10 = (j0     < len) ? __expf(acc[nt][2] - ca * fabsf(ti1 - tj0)) : 0.f;
                float e11 = (j0 + 1 < len) ? __expf(acc[nt][3] - ca * fabsf(ti1 - tj1)) : 0.f;
                acc[nt][0] = e00; acc[nt][1] = e01; acc[nt][2] = e10; acc[nt][3] = e11;
                s0 += e00 + e01; s1 += e10 + e11;
            }
        }
        s0 += __shfl_xor_sync(~0u, s0, 1); s0 += __shfl_xor_sync(~0u, s0, 2);
        s1 += __shfl_xor_sync(~0u, s1, 1); s1 += __shfl_xor_sync(~0u, s1, 2);
        sc0 = wv[r0] / s0;
        sc1 = wv[r1] / s1;
    }

#pragma unroll
    for (int nt = 0; nt < 16; nt++) {
        float v0 = 0.f, v1 = 0.f;
        if (wact && nt * 8 < len) {
            v0 = acc[nt][0] * sc0 + acc[nt][2] * sc1;
            v1 = acc[nt][1] * sc0 + acc[nt][3] * sc1;
        }
        v0 += __shfl_xor_sync(~0u, v0, 4);  v1 += __shfl_xor_sync(~0u, v1, 4);
        v0 += __shfl_xor_sync(~0u, v0, 8);  v1 += __shfl_xor_sync(~0u, v1, 8);
        v0 += __shfl_xor_sync(~0u, v0, 16); v1 += __shfl_xor_sync(~0u, v1, 16);
        if (g == 0) {
            int j0 = nt * 8 + c4 * 2;
            cs[w * 128 + j0] = v0;
            cs[w * 128 + j0 + 1] = v1;
        }
    }
    __syncthreads();
    if (tid < 128) {
        float p = 0.f;
#pragma unroll
        for (int q = 0; q < 8; q++) p += cs[q * 128 + tid];
        pv[tid] = p;
    }
    CP_WAIT0();
    __syncthreads();

    // ebar_d -> X16[n][70 + d]
    const __nv_bfloat16* base = (tid < 128) ? (Asm + tid) : (Bsm + (tid - 128));
    float a = 0.f;
#pragma unroll 4
    for (int j = 0; j < len; j++)
        a = fmaf(pv[j], __bfloat162float(base[j * SA]), a);
    g_X16[(size_t)n * XK + DEMOd + tid] = __float2bfloat16(a);
}

// ---- K3b: partial logits = relu(X @ Wf + b1) . W2, per 128-col chunk.  grid (16,8) ----
__global__ __launch_bounds__(256, 2) void k3b_H(const float* __restrict__ b1,
                                                const float* __restrict__ W2) {
    extern __shared__ __align__(16) char smraw[];
    __nv_bfloat16* Asm = (__nv_bfloat16*)smraw;
    __nv_bfloat16* Bsm = Asm + 128 * SA;
    u32 smA = (u32)__cvta_generic_to_shared(Asm);
    u32 smB = (u32)__cvta_generic_to_shared(Bsm);

    int r0 = blockIdx.x * 128, c0 = blockIdx.y * 128;
    int tid = threadIdx.x;
    int w = tid >> 5, lane = tid & 31;
    int g = lane >> 2, c4 = lane & 3;
    int warpRow = w * 16;
    u32 aAddr = smA + a_lane_off(lane, warpRow) * 2;
    u32 bAddr = smB + b_lane_off(lane) * 2;

    float acc[16][4];
#pragma unroll
    for (int t = 0; t < 16; t++)
        acc[t][0] = acc[t][1] = acc[t][2] = acc[t][3] = 0.f;

    for (int p = 0; p < 3; p++) {
        __syncthreads();
#pragma unroll
        for (int it = 0; it < 8; it++) {
            int id = tid + it * 256;
            int row = id >> 4, seg = id & 15;
            const char* gA = (const char*)(g_X16 + (size_t)(r0 + row) * XK + p * 128) + seg * 16;
            const char* gB = (const char*)(g_WfT16 + (size_t)(c0 + row) * XK + p * 128) + seg * 16;
            CP_ASYNC16(smA + (row * SA + seg * 8) * 2, gA, 16);
            CP_ASYNC16(smB + (row * SA + seg * 8) * 2, gB, 16);
        }
        CP_COMMIT(); CP_WAIT0();
        __syncthreads();
        mma_ks_dense(aAddr, bAddr, acc, 0, 8);
    }
    int rr0 = r0 + warpRow + g, rr1 = rr0 + 8;
    float p0 = 0.f, p1 = 0.f;
#pragma unroll
    for (int nt = 0; nt < 16; nt++) {
        int col = c0 + nt * 8 + c4 * 2;
        float bb0 = b1[col], bb1 = b1[col + 1];
        float w0 = W2[col], w1 = W2[col + 1];
        p0 += fmaxf(acc[nt][0] + bb0, 0.f) * w0 + fmaxf(acc[nt][1] + bb1, 0.f) * w1;
        p1 += fmaxf(acc[nt][2] + bb0, 0.f) * w0 + fmaxf(acc[nt][3] + bb1, 0.f) * w1;
    }
    p0 += __shfl_xor_sync(~0u, p0, 1); p0 += __shfl_xor_sync(~0u, p0, 2);
    p1 += __shfl_xor_sync(~0u, p1, 1); p1 += __shfl_xor_sync(~0u, p1, 2);
    if (c4 == 0) {
        g_part[rr0 * 8 + blockIdx.y] = p0;
        g_part[rr1 * 8 + blockIdx.y] = p1;
    }
}

// ---- K4: logits -> BCE -> deterministic mean + reg ----
__global__ __launch_bounds__(256) void k4_final(const float* __restrict__ labels,
                                                const float* __restrict__ b2,
                                                const float* __restrict__ c_attn,
                                                const float* __restrict__ c_pool,
                                                float* __restrict__ out) {
    __shared__ float red[256];
    int tid = threadIdx.x;
    float s = 0.f;
    for (int i = tid; i < Nn; i += 256) {
        float lg = b2[0];
#pragma unroll
        for (int q = 0; q < 8; q++) lg += g_part[i * 8 + q];
        float y = labels[i];
        float sp = (lg > 0.f) ? lg + log1pf(expf(-lg)) : log1pf(expf(lg));
        s += 2.0f * y * (sp - lg) + (1.0f - y) * sp;
    }
    red[tid] = s;
    __syncthreads();
    for (int st = 128; st; st >>= 1) {
        if (tid < st) red[tid] += red[tid + st];
        __syncthreads();
    }
    if (tid == 0) {
        float ca = c_attn[0], cp = c_pool[0];
        out[0] = red[0] / (float)Nn + ca * ca + cp * cp;
    }
}

static const int MMA_SMEM = 2 * 128 * SA * 2;
static const int K2_SMEM = MMA_SMEM + (8 * 128 + 3 * 128) * 4 + 128 * 4;
static const int PREP_SMEM = KC * SST64 * 4 * 2;

extern "C" void kernel_launch(void* const* d_in, const int* in_sizes, int n_in,
                              void* d_out, int out_size) {
    const float* E       = (const float*)d_in[0];
    const float* Wq      = (const float*)d_in[1];
    const float* Wk      = (const float*)d_in[2];
    const float* Wv      = (const float*)d_in[3];
    const float* c_attn  = (const float*)d_in[4];
    const float* c_pool  = (const float*)d_in[5];
    const float* W1      = (const float*)d_in[6];
    const float* b1      = (const float*)d_in[7];
    const float* W2      = (const float*)d_in[8];
    const float* b2      = (const float*)d_in[9];
    const float* demo    = (const float*)d_in[10];
    const float* ht      = (const float*)d_in[11];
    const float* et      = (const float*)d_in[12];
    const float* labels  = (const float*)d_in[13];
    const int*   codes   = (const int*)d_in[14];
    const int*   lengths = (const int*)d_in[15];
    float* out = (float*)d_out;

    cudaFuncSetAttribute(k1x, cudaFuncAttributeMaxDynamicSharedMemorySize, MMA_SMEM);
    cudaFuncSetAttribute(k2_attn, cudaFuncAttributeMaxDynamicSharedMemorySize, K2_SMEM);
    cudaFuncSetAttribute(k3b_H, cudaFuncAttributeMaxDynamicSharedMemorySize, MMA_SMEM);

    k_dummy<<<1, 32>>>();   // shifts the ncu capture slot onto k2_attn
    k_prep<<<2691, 256, PREP_SMEM>>>(E, Wq, Wk, Wv, W1, demo, lengths);
    k1x<<<330, 256, MMA_SMEM>>>();
    k2_attn<<<Nn, 256, K2_SMEM>>>(codes, ht, et, lengths, c_attn, c_pool);
    k3b_H<<<dim3(16, 8), 256, MMA_SMEM>>>(b1, W2);
    k4_final<<<1, 256>>>(labels, b2, c_attn, c_pool, out);
}

// round 15
// speedup vs baseline: 1.5366x; 1.0147x over previous
#include <cuda_runtime.h>
#include <cuda_bf16.h>
#include <math.h>

#define Vv 20000
#define Lh 128
#define Dd 256
#define DEMOd 70
#define HIDd 1024
#define Nn 2048
#define KC 32
#define SST64 68
#define SA 136     // bf16 operand panel stride (272B, 16B-aligned, conflict-free LDSM)
#define XK 384

typedef unsigned long long u64;
typedef unsigned int u32;

__device__ __forceinline__ u64 ffma2(u64 a, u64 b, u64 c) {
    u64 d; asm("fma.rn.f32x2 %0,%1,%2,%3;" : "=l"(d) : "l"(a), "l"(b), "l"(c)); return d;
}
__device__ __forceinline__ u64 splat2(float x) {
    u64 d; asm("mov.b64 %0,{%1,%1};" : "=l"(d) : "f"(x)); return d;
}
__device__ __forceinline__ u64 pk(float x, float y) {
    u64 d; asm("mov.b64 %0,{%1,%2};" : "=l"(d) : "f"(x), "f"(y)); return d;
}
__device__ __forceinline__ float2 unpk(u64 v) {
    float2 r; asm("mov.b64 {%0,%1},%2;" : "=f"(r.x), "=f"(r.y) : "l"(v)); return r;
}
__device__ __forceinline__ u32 pack_bf16(float lo, float hi) {
    u32 r; asm("cvt.rn.bf16x2.f32 %0, %1, %2;" : "=r"(r) : "f"(hi), "f"(lo)); return r;
}
__device__ __forceinline__ void mma_bf16(float* d, const u32* a, const u32* b) {
    asm volatile(
        "mma.sync.aligned.m16n8k16.row.col.f32.bf16.bf16.f32 "
        "{%0,%1,%2,%3},{%4,%5,%6,%7},{%8,%9},{%0,%1,%2,%3};"
        : "+f"(d[0]), "+f"(d[1]), "+f"(d[2]), "+f"(d[3])
        : "r"(a[0]), "r"(a[1]), "r"(a[2]), "r"(a[3]), "r"(b[0]), "r"(b[1]));
}
__device__ __forceinline__ void ldsm4(u32& r0, u32& r1, u32& r2, u32& r3, u32 a) {
    asm volatile("ldmatrix.sync.aligned.m8n8.x4.shared.b16 {%0,%1,%2,%3},[%4];"
                 : "=r"(r0), "=r"(r1), "=r"(r2), "=r"(r3) : "r"(a));
}
#define CP_ASYNC16(dst, src, sz) \
    asm volatile("cp.async.cg.shared.global [%0], [%1], 16, %2;" :: "r"(dst), "l"(src), "r"(sz))
#define CP_COMMIT() asm volatile("cp.async.commit_group;")
#define CP_WAIT0()  asm volatile("cp.async.wait_group 0;" ::: "memory")
#define CP_WAIT1()  asm volatile("cp.async.wait_group 1;" ::: "memory")

// ---------- device scratch ----------
__device__ __nv_bfloat16 g_E16[Vv * Dd];
__device__ __nv_bfloat16 g_EM16[Vv * Dd];
__device__ __nv_bfloat16 g_M16T[Dd * Dd];
__device__ __nv_bfloat16 g_Wv16[Dd * Dd];
__device__ __nv_bfloat16 g_W1rT[HIDd * Dd];
__device__ __nv_bfloat16 g_WfT16[HIDd * XK];
__device__ __nv_bfloat16 g_X16[Nn * XK];
__device__ float g_part[Nn * 8];
__device__ int g_perm[Nn];

__device__ __forceinline__ u32 a_lane_off(int lane, int warpRow) {
    return (u32)((warpRow + (lane & 15)) * SA + ((lane >> 4) << 3));
}
__device__ __forceinline__ u32 b_lane_off(int lane) {
    return (u32)(((lane & 7) + ((lane >> 4) << 3)) * SA + (((lane >> 3) & 1) << 3));
}

__device__ __forceinline__ void mma_ks_dense(u32 aAddr, u32 bAddr, float acc[16][4],
                                             int ks0, int ks1) {
    for (int ks = ks0; ks < ks1; ks++) {
        u32 a[4]; ldsm4(a[0], a[1], a[2], a[3], aAddr + ks * 32);
#pragma unroll
        for (int nt2 = 0; nt2 < 8; nt2++) {
            u32 b[4]; ldsm4(b[0], b[1], b[2], b[3], bAddr + nt2 * (16 * SA * 2) + ks * 32);
            mma_bf16(acc[2 * nt2], a, b);
            mma_bf16(acc[2 * nt2 + 1], a, b + 2);
        }
    }
}

// ---- dummy: shifts capture slot so k2 is the 4th launch ----
__global__ void k_dummy() {}

// ============ merged prep kernel ============
__global__ __launch_bounds__(256) void k_prep(
    const float* __restrict__ E, const float* __restrict__ Wq,
    const float* __restrict__ Wk, const float* __restrict__ Wv,
    const float* __restrict__ W1, const float* __restrict__ demo,
    const int* __restrict__ lengths) {
    extern __shared__ __align__(16) char psm[];
    int b = blockIdx.x, tid = threadIdx.x;

    if (b < 16) {                     // ---- M16T = (Wq Wk^T / 16)^T bf16
        float* As = (float*)psm;
        float* Bs = As + KC * SST64;
        int r0 = (b & 3) * 64, c0 = (b >> 2) * 64;
        int ty = tid >> 4, tx = tid & 15;
        int i0 = ty * 4, j0 = tx * 4;
        u64 acc[2][4];
#pragma unroll
        for (int a = 0; a < 2; a++)
#pragma unroll
            for (int c = 0; c < 4; c++) acc[a][c] = splat2(0.f);
        for (int k0 = 0; k0 < Dd; k0 += KC) {
            __syncthreads();
#pragma unroll
            for (int r = 0; r < 8; r++) {
                int idx = tid + r * 256;
                int i = idx >> 5, k = idx & 31;
                As[k * SST64 + i] = Wq[(r0 + i) * Dd + k0 + k];
                Bs[k * SST64 + i] = Wk[(c0 + i) * Dd + k0 + k];
            }
            __syncthreads();
#pragma unroll
            for (int k = 0; k < KC; k++) {
                float4 a0 = *(const float4*)(As + k * SST64 + i0);
                float4 b0 = *(const float4*)(Bs + k * SST64 + j0);
                u64 av[2] = {pk(a0.x, a0.y), pk(a0.z, a0.w)};
                float bv[4] = {b0.x, b0.y, b0.z, b0.w};
#pragma unroll
                for (int cc = 0; cc < 4; cc++) {
                    u64 bs = splat2(bv[cc]);
#pragma unroll
                    for (int a = 0; a < 2; a++) acc[a][cc] = ffma2(av[a], bs, acc[a][cc]);
                }
            }
        }
        const float sc = 1.0f / 16.0f;
#pragma unroll
        for (int a = 0; a < 2; a++)
#pragma unroll
            for (int c = 0; c < 4; c++) {
                float2 v = unpk(acc[a][c]);
                int row = r0 + i0 + 2 * a, col = c0 + j0 + c;
                g_M16T[col * Dd + row]     = __float2bfloat16(v.x * sc);
                g_M16T[col * Dd + row + 1] = __float2bfloat16(v.y * sc);
            }
    } else if (b < 1266) {            // ---- e16 (4 float4 per thread)
        int base = (b - 16) * 1024;
#pragma unroll
        for (int j = 0; j < 4; j++) {
            int idx = base + j * 256 + tid;
            float4 v = ((const float4*)E)[idx];
            uint2 o;
            o.x = pack_bf16(v.x, v.y);
            o.y = pack_bf16(v.z, v.w);
            ((uint2*)g_E16)[idx] = o;
        }
    } else if (b < 1282) {            // ---- Wv convert
        int base = (b - 1266) * 1024;
#pragma unroll
        for (int j = 0; j < 4; j++) {
            int idx = base + j * 256 + tid;
            float4 v = ((const float4*)Wv)[idx];
            uint2 o;
            o.x = pack_bf16(v.x, v.y);
            o.y = pack_bf16(v.z, v.w);
            ((uint2*)g_Wv16)[idx] = o;
        }
    } else if (b < 1666) {            // ---- W1^T split
        float* t = (float*)psm;
        int local = b - 1282;
        int k0 = (local % 12) * 32, h0 = (local / 12) * 32;
        int tx = tid & 31, ty = tid >> 5;
#pragma unroll
        for (int i = 0; i < 4; i++) {
            int k = k0 + ty + i * 8;
            t[(ty + i * 8) * 33 + tx] = (k < DEMOd + Dd) ? W1[k * HIDd + h0 + tx] : 0.f;
        }
        __syncthreads();
#pragma unroll
        for (int i = 0; i < 4; i++) {
            int h = h0 + ty + i * 8;
            int kk = k0 + tx;
            float v = t[tx * 33 + ty + i * 8];
            if (kk < DEMOd)
                g_WfT16[h * XK + kk] = __float2bfloat16(v);
            else if (kk < DEMOd + Dd)
                g_W1rT[h * Dd + kk - DEMOd] = __float2bfloat16(v);
            else
                g_WfT16[h * XK + kk] = __float2bfloat16(0.f);
        }
    } else if (b < 2690) {            // ---- X16 demo cols + zero pad
        int local = b - 1666;
        int r = local * 2 + (tid >> 7);
        int t = tid & 127;
        if (t < DEMOd) g_X16[r * XK + t] = __float2bfloat16(demo[r * DEMOd + t]);
        else           g_X16[r * XK + 256 + t] = __float2bfloat16(0.f);
    } else {                          // ---- LPT sort
        __shared__ int hist[129], base[129];
        for (int c = tid; c < 129; c += 256) hist[c] = 0;
        __syncthreads();
        for (int i = tid; i < Nn; i += 256) atomicAdd(&hist[128 - lengths[i]], 1);
        __syncthreads();
        if (tid == 0) { int s = 0; for (int c = 0; c < 129; c++) { base[c] = s; s += hist[c]; } }
        __syncthreads();
        for (int i = tid; i < Nn; i += 256) {
            int pos = atomicAdd(&base[128 - lengths[i]], 1);
            g_perm[pos] = i;
        }
    }
}

// ---- K1x: blocks [0,314) EM GEMM, [314,330) Wcomb GEMM ----
__global__ __launch_bounds__(256, 2) void k1x() {
    extern __shared__ __align__(16) char smraw[];
    __nv_bfloat16* Asm = (__nv_bfloat16*)smraw;
    __nv_bfloat16* Bsm = Asm + 128 * SA;
    u32 smA = (u32)__cvta_generic_to_shared(Asm);
    u32 smB = (u32)__cvta_generic_to_shared(Bsm);

    int bx = blockIdx.x;
    int tid = threadIdx.x;
    int w = tid >> 5, lane = tid & 31;
    int g = lane >> 2, c4 = lane & 3;
    int warpRow = w * 16;
    u32 aAddr = smA + a_lane_off(lane, warpRow) * 2;
    u32 bAddr = smB + b_lane_off(lane) * 2;

    float acc[16][4];
#pragma unroll
    for (int t = 0; t < 16; t++)
        acc[t][0] = acc[t][1] = acc[t][2] = acc[t][3] = 0.f;

    if (bx < 314) {                   // ======== EM16 = E16 @ M ========
        int r0 = (bx % 157) * 128, c0 = (bx / 157) * 128;
        for (int p = 0; p < 2; p++) {
            __syncthreads();
#pragma unroll
            for (int half = 0; half < 2; half++) {
#pragma unroll
                for (int it = 0; it < 4; it++) {
                    int id = tid + it * 256;
                    int row = id >> 3, seg = (id & 7) + half * 8;
                    int ra = r0 + row;
                    const char* gA = (const char*)(g_E16 + (size_t)ra * Dd + p * 128) + seg * 16;
                    const char* gB = (const char*)(g_M16T + (size_t)(c0 + row) * Dd + p * 128) + seg * 16;
                    u32 off = (u32)(row * SA + seg * 8) * 2;
                    CP_ASYNC16(smA + off, gA, (ra < Vv) ? 16 : 0);
                    CP_ASYNC16(smB + off, gB, 16);
                }
                CP_COMMIT();
            }
            CP_WAIT1();
            __syncthreads();
            mma_ks_dense(aAddr, bAddr, acc, 0, 4);
            CP_WAIT0();
            __syncthreads();
            mma_ks_dense(aAddr, bAddr, acc, 4, 8);
        }
        int rr0 = r0 + warpRow + g, rr1 = rr0 + 8;
#pragma unroll
        for (int nt = 0; nt < 16; nt++) {
            int cc = c0 + nt * 8 + c4 * 2;
            if (rr0 < Vv)
                *(u32*)(g_EM16 + (size_t)rr0 * Dd + cc) = pack_bf16(acc[nt][0], acc[nt][1]);
            if (rr1 < Vv)
                *(u32*)(g_EM16 + (size_t)rr1 * Dd + cc) = pack_bf16(acc[nt][2], acc[nt][3]);
        }
    } else {                          // ======== WfT[:,70:326) = (Wv @ W1r)^T ========
        int bb = bx - 314;
        int h0 = (bb & 7) * 128, k0 = (bb >> 3) * 128;
        for (int p = 0; p < 2; p++) {
            __syncthreads();
#pragma unroll
            for (int it = 0; it < 8; it++) {
                int id = tid + it * 256;
                int row = id >> 4, seg = id & 15;
                const char* gA = (const char*)(g_W1rT + (size_t)(h0 + row) * Dd + p * 128) + seg * 16;
                const char* gB = (const char*)(g_Wv16 + (size_t)(k0 + row) * Dd + p * 128) + seg * 16;
                CP_ASYNC16(smA + (row * SA + seg * 8) * 2, gA, 16);
                CP_ASYNC16(smB + (row * SA + seg * 8) * 2, gB, 16);
            }
            CP_COMMIT(); CP_WAIT0();
            __syncthreads();
            mma_ks_dense(aAddr, bAddr, acc, 0, 8);
        }
        int rr0 = h0 + warpRow + g, rr1 = rr0 + 8;
#pragma unroll
        for (int nt = 0; nt < 16; nt++) {
            int cc = DEMOd + k0 + nt * 8 + c4 * 2;
            *(u32*)(g_WfT16 + (size_t)rr0 * XK + cc) = pack_bf16(acc[nt][0], acc[nt][1]);
            *(u32*)(g_WfT16 + (size_t)rr1 * XK + cc) = pack_bf16(acc[nt][2], acc[nt][3]);
        }
    }
}

// ---- K2: per-sample attention + pooling.  512 threads: 8 rowGroups x 2 colHalves ----
__global__ __launch_bounds__(512, 2) void k2_attn(
    const int* __restrict__ codes,
    const float* __restrict__ ht, const float* __restrict__ et,
    const int* __restrict__ lengths, const float* __restrict__ c_attn,
    const float* __restrict__ c_pool) {
    extern __shared__ __align__(16) char smraw[];
    __nv_bfloat16* Asm = (__nv_bfloat16*)smraw;         // t = EM16 gather
    __nv_bfloat16* Bsm = Asm + 128 * SA;                // emb = E16 gather
    float* cs = (float*)(Bsm + 128 * SA);               // 8*128 col partials (reused for ebar)
    float* rs = cs + 8 * 128;                           // 2*128 row-sum partials
    float* wv = rs + 2 * 128;
    float* pv = wv + 128;
    float* tv = pv + 128;
    int*   cd = (int*)(tv + 128);
    u32 smA = (u32)__cvta_generic_to_shared(Asm);
    u32 smB = (u32)__cvta_generic_to_shared(Bsm);

    int n = g_perm[blockIdx.x];
    int tid = threadIdx.x;
    int len = lengths[n];
    int w = tid >> 5, lane = tid & 31;
    int g = lane >> 2, c4 = lane & 3;
    int rg = w & 7, ch = w >> 3;      // rowGroup, colHalf
    int warpRow = rg * 16;
    int cb = ch * 64;                 // column base

    if (tid < 128) {
        cd[tid] = codes[n * Lh + tid];
        tv[tid] = ht[n * Lh + tid];
        wv[tid] = 0.f;
    }
    __syncthreads();

    if (tid < 32) {
        float cp = c_pool[0], e_t = et[n];
        float ssum = 0.f;
        for (int i = tid; i < len; i += 32) {
            float e = __expf(-cp * (e_t - tv[i]));
            wv[i] = e; ssum += e;
        }
#pragma unroll
        for (int o = 16; o; o >>= 1) ssum += __shfl_xor_sync(~0u, ssum, o);
        float inv = 1.f / ssum;
        for (int i = tid; i < len; i += 32) wv[i] *= inv;
    }

    bool wact = warpRow < len;
    int lim = (len + 15) & ~15;
    u32 aAddr = smA + a_lane_off(lane, warpRow) * 2;
    u32 bAddr = smB + b_lane_off(lane) * 2 + (u32)(cb * SA * 2);

    float acc[8][4];
#pragma unroll
    for (int t = 0; t < 8; t++)
        acc[t][0] = acc[t][1] = acc[t][2] = acc[t][3] = 0.f;

    for (int p = 0; p < 2; p++) {
        __syncthreads();
#pragma unroll
        for (int half = 0; half < 2; half++) {
#pragma unroll
            for (int it = 0; it < 2; it++) {
                int id = tid + it * 512;
                int row = id >> 3, seg = (id & 7) + half * 8;
                if (row < lim) {
                    int c = cd[row];
                    const char* gA = (const char*)(g_EM16 + (size_t)c * Dd + p * 128) + seg * 16;
                    const char* gB = (const char*)(g_E16 + (size_t)c * Dd + p * 128) + seg * 16;
                    u32 off = (u32)(row * SA + seg * 8) * 2;
                    int sz = (row < len) ? 16 : 0;
                    CP_ASYNC16(smA + off, gA, sz);
                    CP_ASYNC16(smB + off, gB, sz);
                }
            }
            CP_COMMIT();
        }
        CP_WAIT1();
        __syncthreads();
        if (wact) {
            for (int ks = 0; ks < 4; ks++) {
                u32 a[4]; ldsm4(a[0], a[1], a[2], a[3], aAddr + ks * 32);
#pragma unroll
                for (int nt2 = 0; nt2 < 4; nt2++) {
                    if (cb + nt2 * 16 < len) {
                        u32 b[4];
                        ldsm4(b[0], b[1], b[2], b[3], bAddr + nt2 * (16 * SA * 2) + ks * 32);
                        mma_bf16(acc[2 * nt2], a, b);
                        if (cb + nt2 * 16 + 8 < len) mma_bf16(acc[2 * nt2 + 1], a, b + 2);
                    }
                }
            }
        }
        CP_WAIT0();
        __syncthreads();
        if (wact) {
            for (int ks = 4; ks < 8; ks++) {
                u32 a[4]; ldsm4(a[0], a[1], a[2], a[3], aAddr + ks * 32);
#pragma unroll
                for (int nt2 = 0; nt2 < 4; nt2++) {
                    if (cb + nt2 * 16 < len) {
                        u32 b[4];
                        ldsm4(b[0], b[1], b[2], b[3], bAddr + nt2 * (16 * SA * 2) + ks * 32);
                        mma_bf16(acc[2 * nt2], a, b);
                        if (cb + nt2 * 16 + 8 < len) mma_bf16(acc[2 * nt2 + 1], a, b + 2);
                    }
                }
            }
        }
    }

    // reload E16 k-half0 into Asm (overlap with softmax); rows >= len never read later
    __syncthreads();
#pragma unroll
    for (int it = 0; it < 4; it++) {
        int id = tid + it * 512;
        int row = id >> 4, seg = id & 15;
        if (row < len) {
            int c = cd[row];
            const char* gB = (const char*)(g_E16 + (size_t)c * Dd) + seg * 16;
            CP_ASYNC16(smA + (u32)(row * SA + seg * 8) * 2, gB, 16);
        }
    }
    CP_COMMIT();

    // exp + per-col-half row sums
    int r0 = warpRow + g, r1 = r0 + 8;
    float s0 = 0.f, s1 = 0.f;
    if (wact) {
        float ca = c_attn[0];
        float ti0 = tv[r0], ti1 = tv[r1];
#pragma unroll
        for (int nt = 0; nt < 8; nt++) {
            int j0 = cb + nt * 8 + c4 * 2;
            if (cb + nt * 8 < len) {
                float tj0 = tv[j0], tj1 = tv[j0 + 1];
                float e00 = (j0     < len) ? __expf(acc[nt][0] - ca * fabsf(ti0 - tj0)) : 0.f;
                float e01 = (j0 + 1 < len) ? __expf(acc[nt][1] - ca * fabsf(ti0 - tj1)) : 0.f;
                float e10 = (j0     < len) ? __expf(acc[nt][2] - ca * fabsf(ti1 - tj0)) : 0.f;
                float e11 = (j0 + 1 < len) ? __expf(acc[nt][3] - ca * fabsf(ti1 - tj1)) : 0.f;
                acc[nt][0] = e00; acc[nt][1] = e01; acc[nt][2] = e10; acc[nt][3] = e11;
                s0 += e00 + e01; s1 += e10 + e11;
            }
        }
        s0 += __shfl_xor_sync(~0u, s0, 1); s0 += __shfl_xor_sync(~0u, s0, 2);
        s1 += __shfl_xor_sync(~0u, s1, 1); s1 += __shfl_xor_sync(~0u, s1, 2);
        if (c4 == 0) { rs[ch * 128 + r0] = s0; rs[ch * 128 + r1] = s1; }
    }
    __syncthreads();

    float sc0 = 0.f, sc1 = 0.f;
    if (wact) {
        float t0 = s0 + rs[(1 - ch) * 128 + r0];
        float t1 = s1 + rs[(1 - ch) * 128 + r1];
        sc0 = wv[r0] / t0;            // wv = 0 for invalid rows -> 0
        sc1 = wv[r1] / t1;
    }

    // column partials (per warp over its 16 rows), cross-rowGroup reduce via cs
#pragma unroll
    for (int nt = 0; nt < 8; nt++) {
        float v0 = 0.f, v1 = 0.f;
        if (wact && cb + nt * 8 < len) {
            v0 = acc[nt][0] * sc0 + acc[nt][2] * sc1;
            v1 = acc[nt][1] * sc0 + acc[nt][3] * sc1;
        }
        v0 += __shfl_xor_sync(~0u, v0, 4);  v1 += __shfl_xor_sync(~0u, v1, 4);
        v0 += __shfl_xor_sync(~0u, v0, 8);  v1 += __shfl_xor_sync(~0u, v1, 8);
        v0 += __shfl_xor_sync(~0u, v0, 16); v1 += __shfl_xor_sync(~0u, v1, 16);
        if (g == 0) {
            int j0 = cb + nt * 8 + c4 * 2;
            cs[rg * 128 + j0] = v0;
            cs[rg * 128 + j0 + 1] = v1;
        }
    }
    __syncthreads();
    if (tid < 128) {
        float p = 0.f;
#pragma unroll
        for (int q = 0; q < 8; q++) p += cs[q * 128 + tid];
        pv[tid] = p;
    }
    CP_WAIT0();
    __syncthreads();

    // ebar: split j-range across the two 256-thread halves (deterministic)
    {
        int hs = tid >> 8;            // 0 or 1
        int d = tid & 255;
        int h = len >> 1;
        int jstart = hs ? h : 0;
        int jend = hs ? len : h;
        const __nv_bfloat16* base = (d < 128) ? (Asm + d) : (Bsm + (d - 128));
        float a = 0.f;
#pragma unroll 4
        for (int j = jstart; j < jend; j++)
            a = fmaf(pv[j], __bfloat162float(base[j * SA]), a);
        if (hs) cs[d] = a;
        __syncthreads();
        if (!hs)
            g_X16[(size_t)n * XK + DEMOd + d] = __float2bfloat16(a + cs[d]);
    }
}

// ---- K3b: partial logits = relu(X @ Wf + b1) . W2.  grid (16,8) ----
__global__ __launch_bounds__(256, 2) void k3b_H(const float* __restrict__ b1,
                                                const float* __restrict__ W2) {
    extern __shared__ __align__(16) char smraw[];
    __nv_bfloat16* Asm = (__nv_bfloat16*)smraw;
    __nv_bfloat16* Bsm = Asm + 128 * SA;
    u32 smA = (u32)__cvta_generic_to_shared(Asm);
    u32 smB = (u32)__cvta_generic_to_shared(Bsm);

    int r0 = blockIdx.x * 128, c0 = blockIdx.y * 128;
    int tid = threadIdx.x;
    int w = tid >> 5, lane = tid & 31;
    int g = lane >> 2, c4 = lane & 3;
    int warpRow = w * 16;
    u32 aAddr = smA + a_lane_off(lane, warpRow) * 2;
    u32 bAddr = smB + b_lane_off(lane) * 2;

    float acc[16][4];
#pragma unroll
    for (int t = 0; t < 16; t++)
        acc[t][0] = acc[t][1] = acc[t][2] = acc[t][3] = 0.f;

    for (int p = 0; p < 3; p++) {
        __syncthreads();
#pragma unroll
        for (int it = 0; it < 8; it++) {
            int id = tid + it * 256;
            int row = id >> 4, seg = id & 15;
            const char* gA = (const char*)(g_X16 + (size_t)(r0 + row) * XK + p * 128) + seg * 16;
            const char* gB = (const char*)(g_WfT16 + (size_t)(c0 + row) * XK + p * 128) + seg * 16;
            CP_ASYNC16(smA + (row * SA + seg * 8) * 2, gA, 16);
            CP_ASYNC16(smB + (row * SA + seg * 8) * 2, gB, 16);
        }
        CP_COMMIT(); CP_WAIT0();
        __syncthreads();
        mma_ks_dense(aAddr, bAddr, acc, 0, 8);
    }
    int rr0 = r0 + warpRow + g, rr1 = rr0 + 8;
    float p0 = 0.f, p1 = 0.f;
#pragma unroll
    for (int nt = 0; nt < 16; nt++) {
        int col = c0 + nt * 8 + c4 * 2;
        float bb0 = b1[col], bb1 = b1[col + 1];
        float w0 = W2[col], w1 = W2[col + 1];
        p0 += fmaxf(acc[nt][0] + bb0, 0.f) * w0 + fmaxf(acc[nt][1] + bb1, 0.f) * w1;
        p1 += fmaxf(acc[nt][2] + bb0, 0.f) * w0 + fmaxf(acc[nt][3] + bb1, 0.f) * w1;
    }
    p0 += __shfl_xor_sync(~0u, p0, 1); p0 += __shfl_xor_sync(~0u, p0, 2);
    p1 += __shfl_xor_sync(~0u, p1, 1); p1 += __shfl_xor_sync(~0u, p1, 2);
    if (c4 == 0) {
        g_part[rr0 * 8 + blockIdx.y] = p0;
        g_part[rr1 * 8 + blockIdx.y] = p1;
    }
}

// ---- K4: logits -> BCE -> deterministic mean + reg ----
__global__ __launch_bounds__(256) void k4_final(const float* __restrict__ labels,
                                                const float* __restrict__ b2,
                                                const float* __restrict__ c_attn,
                                                const float* __restrict__ c_pool,
                                                float* __restrict__ out) {
    __shared__ float red[256];
    int tid = threadIdx.x;
    float s = 0.f;
    for (int i = tid; i < Nn; i += 256) {
        float lg = b2[0];
#pragma unroll
        for (int q = 0; q < 8; q++) lg += g_part[i * 8 + q];
        float y = labels[i];
        float sp = (lg > 0.f) ? lg + log1pf(expf(-lg)) : log1pf(expf(lg));
        s += 2.0f * y * (sp - lg) + (1.0f - y) * sp;
    }
    red[tid] = s;
    __syncthreads();
    for (int st = 128; st; st >>= 1) {
        if (tid < st) red[tid] += red[tid + st];
        __syncthreads();
    }
    if (tid == 0) {
        float ca = c_attn[0], cp = c_pool[0];
        out[0] = red[0] / (float)Nn + ca * ca + cp * cp;
    }
}

static const int MMA_SMEM = 2 * 128 * SA * 2;
static const int K2_SMEM = MMA_SMEM + (8 * 128 + 2 * 128 + 3 * 128) * 4 + 128 * 4;  // 76800
static const int PREP_SMEM = KC * SST64 * 4 * 2;

extern "C" void kernel_launch(void* const* d_in, const int* in_sizes, int n_in,
                              void* d_out, int out_size) {
    const float* E       = (const float*)d_in[0];
    const float* Wq      = (const float*)d_in[1];
    const float* Wk      = (const float*)d_in[2];
    const float* Wv      = (const float*)d_in[3];
    const float* c_attn  = (const float*)d_in[4];
    const float* c_pool  = (const float*)d_in[5];
    const float* W1      = (const float*)d_in[6];
    const float* b1      = (const float*)d_in[7];
    const float* W2      = (const float*)d_in[8];
    const float* b2      = (const float*)d_in[9];
    const float* demo    = (const float*)d_in[10];
    const float* ht      = (const float*)d_in[11];
    const float* et      = (const float*)d_in[12];
    const float* labels  = (const float*)d_in[13];
    const int*   codes   = (const int*)d_in[14];
    const int*   lengths = (const int*)d_in[15];
    float* out = (float*)d_out;

    cudaFuncSetAttribute(k1x, cudaFuncAttributeMaxDynamicSharedMemorySize, MMA_SMEM);
    cudaFuncSetAttribute(k2_attn, cudaFuncAttributeMaxDynamicSharedMemorySize, K2_SMEM);
    cudaFuncSetAttribute(k3b_H, cudaFuncAttributeMaxDynamicSharedMemorySize, MMA_SMEM);

    k_dummy<<<1, 32>>>();   // keeps k2 in the ncu capture slot
    k_prep<<<2691, 256, PREP_SMEM>>>(E, Wq, Wk, Wv, W1, demo, lengths);
    k1x<<<330, 256, MMA_SMEM>>>();
    k2_attn<<<Nn, 512, K2_SMEM>>>(codes, ht, et, lengths, c_attn, c_pool);
    k3b_H<<<dim3(16, 8), 256, MMA_SMEM>>>(b1, W2);
    k4_final<<<1, 256>>>(labels, b2, c_attn, c_pool, out);
}

// round 17
// speedup vs baseline: 1.5402x; 1.0024x over previous
#include <cuda_runtime.h>
#include <cuda_bf16.h>
#include <math.h>

#define Vv 20000
#define Lh 128
#define Dd 256
#define DEMOd 70
#define HIDd 1024
#define Nn 2048
#define KC 32
#define SST64 68
#define SA 136     // bf16 operand panel stride (272B, 16B-aligned, conflict-free LDSM)
#define XK 384

typedef unsigned long long u64;
typedef unsigned int u32;

__device__ __forceinline__ u64 ffma2(u64 a, u64 b, u64 c) {
    u64 d; asm("fma.rn.f32x2 %0,%1,%2,%3;" : "=l"(d) : "l"(a), "l"(b), "l"(c)); return d;
}
__device__ __forceinline__ u64 splat2(float x) {
    u64 d; asm("mov.b64 %0,{%1,%1};" : "=l"(d) : "f"(x)); return d;
}
__device__ __forceinline__ u64 pk(float x, float y) {
    u64 d; asm("mov.b64 %0,{%1,%2};" : "=l"(d) : "f"(x), "f"(y)); return d;
}
__device__ __forceinline__ float2 unpk(u64 v) {
    float2 r; asm("mov.b64 {%0,%1},%2;" : "=f"(r.x), "=f"(r.y) : "l"(v)); return r;
}
__device__ __forceinline__ u32 pack_bf16(float lo, float hi) {
    u32 r; asm("cvt.rn.bf16x2.f32 %0, %1, %2;" : "=r"(r) : "f"(hi), "f"(lo)); return r;
}
__device__ __forceinline__ void mma_bf16(float* d, const u32* a, const u32* b) {
    asm volatile(
        "mma.sync.aligned.m16n8k16.row.col.f32.bf16.bf16.f32 "
        "{%0,%1,%2,%3},{%4,%5,%6,%7},{%8,%9},{%0,%1,%2,%3};"
        : "+f"(d[0]), "+f"(d[1]), "+f"(d[2]), "+f"(d[3])
        : "r"(a[0]), "r"(a[1]), "r"(a[2]), "r"(a[3]), "r"(b[0]), "r"(b[1]));
}
__device__ __forceinline__ void ldsm4(u32& r0, u32& r1, u32& r2, u32& r3, u32 a) {
    asm volatile("ldmatrix.sync.aligned.m8n8.x4.shared.b16 {%0,%1,%2,%3},[%4];"
                 : "=r"(r0), "=r"(r1), "=r"(r2), "=r"(r3) : "r"(a));
}
#define CP_ASYNC16(dst, src, sz) \
    asm volatile("cp.async.cg.shared.global [%0], [%1], 16, %2;" :: "r"(dst), "l"(src), "r"(sz))
#define CP_COMMIT() asm volatile("cp.async.commit_group;")
#define CP_WAIT0()  asm volatile("cp.async.wait_group 0;" ::: "memory")
#define CP_WAIT1()  asm volatile("cp.async.wait_group 1;" ::: "memory")

// ---------- device scratch ----------
// interleaved per-code row (512 elems = 1KB):
//   [0:128) EM khalf0 | [128:256) E khalf0 | [256:384) EM khalf1 | [384:512) E khalf1
__device__ __nv_bfloat16 g_EE16[(size_t)Vv * 512];
__device__ __nv_bfloat16 g_M16T[Dd * Dd];
__device__ __nv_bfloat16 g_Wv16[Dd * Dd];
__device__ __nv_bfloat16 g_W1rT[HIDd * Dd];
__device__ __nv_bfloat16 g_WfT16[HIDd * XK];
__device__ __nv_bfloat16 g_X16[Nn * XK];
__device__ float g_part[Nn * 8];
__device__ int g_perm[Nn];

__device__ __forceinline__ u32 a_lane_off(int lane, int warpRow) {
    return (u32)((warpRow + (lane & 15)) * SA + ((lane >> 4) << 3));
}
__device__ __forceinline__ u32 b_lane_off(int lane) {
    return (u32)(((lane & 7) + ((lane >> 4) << 3)) * SA + (((lane >> 3) & 1) << 3));
}

__device__ __forceinline__ void mma_ks_dense(u32 aAddr, u32 bAddr, float acc[16][4],
                                             int ks0, int ks1) {
    for (int ks = ks0; ks < ks1; ks++) {
        u32 a[4]; ldsm4(a[0], a[1], a[2], a[3], aAddr + ks * 32);
#pragma unroll
        for (int nt2 = 0; nt2 < 8; nt2++) {
            u32 b[4]; ldsm4(b[0], b[1], b[2], b[3], bAddr + nt2 * (16 * SA * 2) + ks * 32);
            mma_bf16(acc[2 * nt2], a, b);
            mma_bf16(acc[2 * nt2 + 1], a, b + 2);
        }
    }
}

// ---- dummy: keeps k2 in the ncu capture slot ----
__global__ void k_dummy() {}

// ============ merged prep kernel ============
__global__ __launch_bounds__(256) void k_prep(
    const float* __restrict__ E, const float* __restrict__ Wq,
    const float* __restrict__ Wk, const float* __restrict__ Wv,
    const float* __restrict__ W1, const float* __restrict__ demo,
    const int* __restrict__ lengths) {
    extern __shared__ __align__(16) char psm[];
    int b = blockIdx.x, tid = threadIdx.x;

    if (b < 16) {                     // ---- M16T = (Wq Wk^T / 16)^T bf16
        float* As = (float*)psm;
        float* Bs = As + KC * SST64;
        int r0 = (b & 3) * 64, c0 = (b >> 2) * 64;
        int ty = tid >> 4, tx = tid & 15;
        int i0 = ty * 4, j0 = tx * 4;
        u64 acc[2][4];
#pragma unroll
        for (int a = 0; a < 2; a++)
#pragma unroll
            for (int c = 0; c < 4; c++) acc[a][c] = splat2(0.f);
        for (int k0 = 0; k0 < Dd; k0 += KC) {
            __syncthreads();
#pragma unroll
            for (int r = 0; r < 8; r++) {
                int idx = tid + r * 256;
                int i = idx >> 5, k = idx & 31;
                As[k * SST64 + i] = Wq[(r0 + i) * Dd + k0 + k];
                Bs[k * SST64 + i] = Wk[(c0 + i) * Dd + k0 + k];
            }
            __syncthreads();
#pragma unroll
            for (int k = 0; k < KC; k++) {
                float4 a0 = *(const float4*)(As + k * SST64 + i0);
                float4 b0 = *(const float4*)(Bs + k * SST64 + j0);
                u64 av[2] = {pk(a0.x, a0.y), pk(a0.z, a0.w)};
                float bv[4] = {b0.x, b0.y, b0.z, b0.w};
#pragma unroll
                for (int cc = 0; cc < 4; cc++) {
                    u64 bs = splat2(bv[cc]);
#pragma unroll
                    for (int a = 0; a < 2; a++) acc[a][cc] = ffma2(av[a], bs, acc[a][cc]);
                }
            }
        }
        const float sc = 1.0f / 16.0f;
#pragma unroll
        for (int a = 0; a < 2; a++)
#pragma unroll
            for (int c = 0; c < 4; c++) {
                float2 v = unpk(acc[a][c]);
                int row = r0 + i0 + 2 * a, col = c0 + j0 + c;
                g_M16T[col * Dd + row]     = __float2bfloat16(v.x * sc);
                g_M16T[col * Dd + row + 1] = __float2bfloat16(v.y * sc);
            }
    } else if (b < 1266) {            // ---- E -> interleaved EE (E sub-blocks)
        int base = (b - 16) * 1024;
#pragma unroll
        for (int j = 0; j < 4; j++) {
            int idx = base + j * 256 + tid;       // float4 index
            float4 v = ((const float4*)E)[idx];
            uint2 o;
            o.x = pack_bf16(v.x, v.y);
            o.y = pack_bf16(v.z, v.w);
            int e4 = idx * 4;                     // element index in E
            int c = e4 >> 8;                      // code row
            int e = e4 & 255;                     // elem within row
            size_t dst = (size_t)c * 512 + ((e >> 7) << 8) + 128 + (e & 127);
            *(uint2*)(g_EE16 + dst) = o;
        }
    } else if (b < 1282) {            // ---- Wv convert
        int base = (b - 1266) * 1024;
#pragma unroll
        for (int j = 0; j < 4; j++) {
            int idx = base + j * 256 + tid;
            float4 v = ((const float4*)Wv)[idx];
            uint2 o;
            o.x = pack_bf16(v.x, v.y);
            o.y = pack_bf16(v.z, v.w);
            ((uint2*)g_Wv16)[idx] = o;
        }
    } else if (b < 1666) {            // ---- W1^T split
        float* t = (float*)psm;
        int local = b - 1282;
        int k0 = (local % 12) * 32, h0 = (local / 12) * 32;
        int tx = tid & 31, ty = tid >> 5;
#pragma unroll
        for (int i = 0; i < 4; i++) {
            int k = k0 + ty + i * 8;
            t[(ty + i * 8) * 33 + tx] = (k < DEMOd + Dd) ? W1[k * HIDd + h0 + tx] : 0.f;
        }
        __syncthreads();
#pragma unroll
        for (int i = 0; i < 4; i++) {
            int h = h0 + ty + i * 8;
            int kk = k0 + tx;
            float v = t[tx * 33 + ty + i * 8];
            if (kk < DEMOd)
                g_WfT16[h * XK + kk] = __float2bfloat16(v);
            else if (kk < DEMOd + Dd)
                g_W1rT[h * Dd + kk - DEMOd] = __float2bfloat16(v);
            else
                g_WfT16[h * XK + kk] = __float2bfloat16(0.f);
        }
    } else if (b < 2690) {            // ---- X16 demo cols + zero pad
        int local = b - 1666;
        int r = local * 2 + (tid >> 7);
        int t = tid & 127;
        if (t < DEMOd) g_X16[r * XK + t] = __float2bfloat16(demo[r * DEMOd + t]);
        else           g_X16[r * XK + 256 + t] = __float2bfloat16(0.f);
    } else {                          // ---- LPT sort
        __shared__ int hist[129], base[129];
        for (int c = tid; c < 129; c += 256) hist[c] = 0;
        __syncthreads();
        for (int i = tid; i < Nn; i += 256) atomicAdd(&hist[128 - lengths[i]], 1);
        __syncthreads();
        if (tid == 0) { int s = 0; for (int c = 0; c < 129; c++) { base[c] = s; s += hist[c]; } }
        __syncthreads();
        for (int i = tid; i < Nn; i += 256) {
            int pos = atomicAdd(&base[128 - lengths[i]], 1);
            g_perm[pos] = i;
        }
    }
}

// ---- K1x: blocks [0,314) EM GEMM, [314,330) Wcomb GEMM ----
__global__ __launch_bounds__(256, 2) void k1x() {
    extern __shared__ __align__(16) char smraw[];
    __nv_bfloat16* Asm = (__nv_bfloat16*)smraw;
    __nv_bfloat16* Bsm = Asm + 128 * SA;
    u32 smA = (u32)__cvta_generic_to_shared(Asm);
    u32 smB = (u32)__cvta_generic_to_shared(Bsm);

    int bx = blockIdx.x;
    int tid = threadIdx.x;
    int w = tid >> 5, lane = tid & 31;
    int g = lane >> 2, c4 = lane & 3;
    int warpRow = w * 16;
    u32 aAddr = smA + a_lane_off(lane, warpRow) * 2;
    u32 bAddr = smB + b_lane_off(lane) * 2;

    float acc[16][4];
#pragma unroll
    for (int t = 0; t < 16; t++)
        acc[t][0] = acc[t][1] = acc[t][2] = acc[t][3] = 0.f;

    if (bx < 314) {                   // ======== EM = E @ M -> EE layout ========
        int r0 = (bx % 157) * 128, c0 = (bx / 157) * 128;
        for (int p = 0; p < 2; p++) {
            __syncthreads();
#pragma unroll
            for (int half = 0; half < 2; half++) {
#pragma unroll
                for (int it = 0; it < 4; it++) {
                    int id = tid + it * 256;
                    int row = id >> 3, seg = (id & 7) + half * 8;
                    int ra = r0 + row;
                    // E row khalf p lives at EE + ra*1024B + p*512B + 256B
                    const char* gA = (const char*)g_EE16 + (size_t)ra * 1024 + p * 512 + 256 + seg * 16;
                    const char* gB = (const char*)(g_M16T + (size_t)(c0 + row) * Dd + p * 128) + seg * 16;
                    u32 off = (u32)(row * SA + seg * 8) * 2;
                    CP_ASYNC16(smA + off, gA, (ra < Vv) ? 16 : 0);
                    CP_ASYNC16(smB + off, gB, 16);
                }
                CP_COMMIT();
            }
            CP_WAIT1();
            __syncthreads();
            mma_ks_dense(aAddr, bAddr, acc, 0, 4);
            CP_WAIT0();
            __syncthreads();
            mma_ks_dense(aAddr, bAddr, acc, 4, 8);
        }
        int rr0 = r0 + warpRow + g, rr1 = rr0 + 8;
        int pout = (c0 == 128) ? 256 : 0;     // EM khalf slot in EE row
#pragma unroll
        for (int nt = 0; nt < 16; nt++) {
            int cc = pout + nt * 8 + c4 * 2;
            if (rr0 < Vv)
                *(u32*)(g_EE16 + (size_t)rr0 * 512 + cc) = pack_bf16(acc[nt][0], acc[nt][1]);
            if (rr1 < Vv)
                *(u32*)(g_EE16 + (size_t)rr1 * 512 + cc) = pack_bf16(acc[nt][2], acc[nt][3]);
        }
    } else {                          // ======== WfT[:,70:326) = (Wv @ W1r)^T ========
        int bb = bx - 314;
        int h0 = (bb & 7) * 128, k0 = (bb >> 3) * 128;
        for (int p = 0; p < 2; p++) {
            __syncthreads();
#pragma unroll
            for (int it = 0; it < 8; it++) {
                int id = tid + it * 256;
                int row = id >> 4, seg = id & 15;
                const char* gA = (const char*)(g_W1rT + (size_t)(h0 + row) * Dd + p * 128) + seg * 16;
                const char* gB = (const char*)(g_Wv16 + (size_t)(k0 + row) * Dd + p * 128) + seg * 16;
                CP_ASYNC16(smA + (row * SA + seg * 8) * 2, gA, 16);
                CP_ASYNC16(smB + (row * SA + seg * 8) * 2, gB, 16);
            }
            CP_COMMIT(); CP_WAIT0();
            __syncthreads();
            mma_ks_dense(aAddr, bAddr, acc, 0, 8);
        }
        int rr0 = h0 + warpRow + g, rr1 = rr0 + 8;
#pragma unroll
        for (int nt = 0; nt < 16; nt++) {
            int cc = DEMOd + k0 + nt * 8 + c4 * 2;
            *(u32*)(g_WfT16 + (size_t)rr0 * XK + cc) = pack_bf16(acc[nt][0], acc[nt][1]);
            *(u32*)(g_WfT16 + (size_t)rr1 * XK + cc) = pack_bf16(acc[nt][2], acc[nt][3]);
        }
    }
}

// ---- K2: per-sample attention + pooling.  512 threads: 8 rowGroups x 2 colHalves ----
__global__ __launch_bounds__(512, 2) void k2_attn(
    const int* __restrict__ codes,
    const float* __restrict__ ht, const float* __restrict__ et,
    const int* __restrict__ lengths, const float* __restrict__ c_attn,
    const float* __restrict__ c_pool) {
    extern __shared__ __align__(16) char smraw[];
    __nv_bfloat16* Asm = (__nv_bfloat16*)smraw;         // t = EM gather
    __nv_bfloat16* Bsm = Asm + 128 * SA;                // emb = E gather
    float* cs = (float*)(Bsm + 128 * SA);               // 8*128 col partials
    float* rs = cs + 8 * 128;                           // 2*128 row-sum partials
    float* wv = rs + 2 * 128;
    float* pv = wv + 128;
    float* tv = pv + 128;
    int*   cd = (int*)(tv + 128);
    u32 smA = (u32)__cvta_generic_to_shared(Asm);
    u32 smB = (u32)__cvta_generic_to_shared(Bsm);

    int n = g_perm[blockIdx.x];
    int tid = threadIdx.x;
    int len = lengths[n];
    int w = tid >> 5, lane = tid & 31;
    int g = lane >> 2, c4 = lane & 3;
    int rg = w & 7, ch = w >> 3;
    int warpRow = rg * 16;
    int cb = ch * 64;

    if (tid < 128) {
        cd[tid] = codes[n * Lh + tid];
        tv[tid] = ht[n * Lh + tid];
        wv[tid] = 0.f;
    }
    __syncthreads();

    bool wact = warpRow < len;
    int lim = (len + 15) & ~15;
    u32 aAddr = smA + a_lane_off(lane, warpRow) * 2;
    u32 bAddr = smB + b_lane_off(lane) * 2 + (u32)(cb * SA * 2);

    float acc[8][4];
#pragma unroll
    for (int t = 0; t < 8; t++)
        acc[t][0] = acc[t][1] = acc[t][2] = acc[t][3] = 0.f;

    // ---- issue phase-0 loads FIRST (interleaved EE: one base per row pair) ----
#pragma unroll
    for (int half = 0; half < 2; half++) {
#pragma unroll
        for (int it = 0; it < 2; it++) {
            int id = tid + it * 512;
            int row = id >> 3, seg = (id & 7) + half * 8;
            if (row < lim) {
                int c = cd[row];
                const char* base = (const char*)g_EE16 + (size_t)c * 1024 + seg * 16;
                u32 off = (u32)(row * SA + seg * 8) * 2;
                int sz = (row < len) ? 16 : 0;
                CP_ASYNC16(smA + off, base, sz);
                CP_ASYNC16(smB + off, base + 256, sz);
            }
        }
        CP_COMMIT();
    }

    // ---- pooling weights: overlapped with phase-0 gather flight ----
    if (tid < 32) {
        float cp = c_pool[0], e_t = et[n];
        float ssum = 0.f;
        for (int i = tid; i < len; i += 32) {
            float e = __expf(-cp * (e_t - tv[i]));
            wv[i] = e; ssum += e;
        }
#pragma unroll
        for (int o = 16; o; o >>= 1) ssum += __shfl_xor_sync(~0u, ssum, o);
        float inv = 1.f / ssum;
        for (int i = tid; i < len; i += 32) wv[i] *= inv;
    }

    for (int p = 0; p < 2; p++) {
        if (p == 1) {
            __syncthreads();   // phase-0 mma done reading panels
#pragma unroll
            for (int half = 0; half < 2; half++) {
#pragma unroll
                for (int it = 0; it < 2; it++) {
                    int id = tid + it * 512;
                    int row = id >> 3, seg = (id & 7) + half * 8;
                    if (row < lim) {
                        int c = cd[row];
                        const char* base = (const char*)g_EE16 + (size_t)c * 1024 + 512 + seg * 16;
                        u32 off = (u32)(row * SA + seg * 8) * 2;
                        int sz = (row < len) ? 16 : 0;
                        CP_ASYNC16(smA + off, base, sz);
                        CP_ASYNC16(smB + off, base + 256, sz);
                    }
                }
                CP_COMMIT();
            }
        }
        CP_WAIT1();
        __syncthreads();
        if (wact) {
            for (int ks = 0; ks < 4; ks++) {
                u32 a[4]; ldsm4(a[0], a[1], a[2], a[3], aAddr + ks * 32);
#pragma unroll
                for (int nt2 = 0; nt2 < 4; nt2++) {
                    if (cb + nt2 * 16 < len) {
                        u32 b[4];
                        ldsm4(b[0], b[1], b[2], b[3], bAddr + nt2 * (16 * SA * 2) + ks * 32);
                        mma_bf16(acc[2 * nt2], a, b);
                        if (cb + nt2 * 16 + 8 < len) mma_bf16(acc[2 * nt2 + 1], a, b + 2);
                    }
                }
            }
        }
        CP_WAIT0();
        __syncthreads();
        if (wact) {
            for (int ks = 4; ks < 8; ks++) {
                u32 a[4]; ldsm4(a[0], a[1], a[2], a[3], aAddr + ks * 32);
#pragma unroll
                for (int nt2 = 0; nt2 < 4; nt2++) {
                    if (cb + nt2 * 16 < len) {
                        u32 b[4];
                        ldsm4(b[0], b[1], b[2], b[3], bAddr + nt2 * (16 * SA * 2) + ks * 32);
                        mma_bf16(acc[2 * nt2], a, b);
                        if (cb + nt2 * 16 + 8 < len) mma_bf16(acc[2 * nt2 + 1], a, b + 2);
                    }
                }
            }
        }
    }

    // reload E khalf0 into Asm (overlap with softmax); rows >= len never read later
    __syncthreads();
#pragma unroll
    for (int it = 0; it < 4; it++) {
        int id = tid + it * 512;
        int row = id >> 4, seg = id & 15;
        if (row < len) {
            int c = cd[row];
            const char* src = (const char*)g_EE16 + (size_t)c * 1024 + 256 + seg * 16;
            CP_ASYNC16(smA + (u32)(row * SA + seg * 8) * 2, src, 16);
        }
    }
    CP_COMMIT();

    // exp + per-col-half row sums
    int r0 = warpRow + g, r1 = r0 + 8;
    float s0 = 0.f, s1 = 0.f;
    if (wact) {
        float ca = c_attn[0];
        float ti0 = tv[r0], ti1 = tv[r1];
#pragma unroll
        for (int nt = 0; nt < 8; nt++) {
            int j0 = cb + nt * 8 + c4 * 2;
            if (cb + nt * 8 < len) {
                float tj0 = tv[j0], tj1 = tv[j0 + 1];
                float e00 = (j0     < len) ? __expf(acc[nt][0] - ca * fabsf(ti0 - tj0)) : 0.f;
                float e01 = (j0 + 1 < len) ? __expf(acc[nt][1] - ca * fabsf(ti0 - tj1)) : 0.f;
                float e10 = (j0     < len) ? __expf(acc[nt][2] - ca * fabsf(ti1 - tj0)) : 0.f;
                float e11 = (j0 + 1 < len) ? __expf(acc[nt][3] - ca * fabsf(ti1 - tj1)) : 0.f;
                acc[nt][0] = e00; acc[nt][1] = e01; acc[nt][2] = e10; acc[nt][3] = e11;
                s0 += e00 + e01; s1 += e10 + e11;
            }
        }
        s0 += __shfl_xor_sync(~0u, s0, 1); s0 += __shfl_xor_sync(~0u, s0, 2);
        s1 += __shfl_xor_sync(~0u, s1, 1); s1 += __shfl_xor_sync(~0u, s1, 2);
        if (c4 == 0) { rs[ch * 128 + r0] = s0; rs[ch * 128 + r1] = s1; }
    }
    __syncthreads();

    float sc0 = 0.f, sc1 = 0.f;
    if (wact) {
        float t0 = s0 + rs[(1 - ch) * 128 + r0];
        float t1 = s1 + rs[(1 - ch) * 128 + r1];
        sc0 = wv[r0] / t0;
        sc1 = wv[r1] / t1;
    }

#pragma unroll
    for (int nt = 0; nt < 8; nt++) {
        float v0 = 0.f, v1 = 0.f;
        if (wact && cb + nt * 8 < len) {
            v0 = acc[nt][0] * sc0 + acc[nt][2] * sc1;
            v1 = acc[nt][1] * sc0 + acc[nt][3] * sc1;
        }
        v0 += __shfl_xor_sync(~0u, v0, 4);  v1 += __shfl_xor_sync(~0u, v1, 4);
        v0 += __shfl_xor_sync(~0u, v0, 8);  v1 += __shfl_xor_sync(~0u, v1, 8);
        v0 += __shfl_xor_sync(~0u, v0, 16); v1 += __shfl_xor_sync(~0u, v1, 16);
        if (g == 0) {
            int j0 = cb + nt * 8 + c4 * 2;
            cs[rg * 128 + j0] = v0;
            cs[rg * 128 + j0 + 1] = v1;
        }
    }
    __syncthreads();
    if (tid < 128) {
        float p = 0.f;
#pragma unroll
        for (int q = 0; q < 8; q++) p += cs[q * 128 + tid];
        pv[tid] = p;
    }
    CP_WAIT0();
    __syncthreads();

    // ebar: split j-range across the two 256-thread halves (deterministic)
    {
        int hs = tid >> 8;
        int d = tid & 255;
        int h = len >> 1;
        int jstart = hs ? h : 0;
        int jend = hs ? len : h;
        const __nv_bfloat16* base = (d < 128) ? (Asm + d) : (Bsm + (d - 128));
        float a = 0.f;
#pragma unroll 4
        for (int j = jstart; j < jend; j++)
            a = fmaf(pv[j], __bfloat162float(base[j * SA]), a);
        if (hs) cs[d] = a;
        __syncthreads();
        if (!hs)
            g_X16[(size_t)n * XK + DEMOd + d] = __float2bfloat16(a + cs[d]);
    }
}

// ---- K3b: partial logits = relu(X @ Wf + b1) . W2.  grid (16,8) ----
__global__ __launch_bounds__(256, 2) void k3b_H(const float* __restrict__ b1,
                                                const float* __restrict__ W2) {
    extern __shared__ __align__(16) char smraw[];
    __nv_bfloat16* Asm = (__nv_bfloat16*)smraw;
    __nv_bfloat16* Bsm = Asm + 128 * SA;
    u32 smA = (u32)__cvta_generic_to_shared(Asm);
    u32 smB = (u32)__cvta_generic_to_shared(Bsm);

    int r0 = blockIdx.x * 128, c0 = blockIdx.y * 128;
    int tid = threadIdx.x;
    int w = tid >> 5, lane = tid & 31;
    int g = lane >> 2, c4 = lane & 3;
    int warpRow = w * 16;
    u32 aAddr = smA + a_lane_off(lane, warpRow) * 2;
    u32 bAddr = smB + b_lane_off(lane) * 2;

    float acc[16][4];
#pragma unroll
    for (int t = 0; t < 16; t++)
        acc[t][0] = acc[t][1] = acc[t][2] = acc[t][3] = 0.f;

    for (int p = 0; p < 3; p++) {
        __syncthreads();
#pragma unroll
        for (int it = 0; it < 8; it++) {
            int id = tid + it * 256;
            int row = id >> 4, seg = id & 15;
            const char* gA = (const char*)(g_X16 + (size_t)(r0 + row) * XK + p * 128) + seg * 16;
            const char* gB = (const char*)(g_WfT16 + (size_t)(c0 + row) * XK + p * 128) + seg * 16;
            CP_ASYNC16(smA + (row * SA + seg * 8) * 2, gA, 16);
            CP_ASYNC16(smB + (row * SA + seg * 8) * 2, gB, 16);
        }
        CP_COMMIT(); CP_WAIT0();
        __syncthreads();
        mma_ks_dense(aAddr, bAddr, acc, 0, 8);
    }
    int rr0 = r0 + warpRow + g, rr1 = rr0 + 8;
    float p0 = 0.f, p1 = 0.f;
#pragma unroll
    for (int nt = 0; nt < 16; nt++) {
        int col = c0 + nt * 8 + c4 * 2;
        float bb0 = b1[col], bb1 = b1[col + 1];
        float w0 = W2[col], w1 = W2[col + 1];
        p0 += fmaxf(acc[nt][0] + bb0, 0.f) * w0 + fmaxf(acc[nt][1] + bb1, 0.f) * w1;
        p1 += fmaxf(acc[nt][2] + bb0, 0.f) * w0 + fmaxf(acc[nt][3] + bb1, 0.f) * w1;
    }
    p0 += __shfl_xor_sync(~0u, p0, 1); p0 += __shfl_xor_sync(~0u, p0, 2);
    p1 += __shfl_xor_sync(~0u, p1, 1); p1 += __shfl_xor_sync(~0u, p1, 2);
    if (c4 == 0) {
        g_part[rr0 * 8 + blockIdx.y] = p0;
        g_part[rr1 * 8 + blockIdx.y] = p1;
    }
}

// ---- K4: logits -> BCE -> deterministic mean + reg ----
__global__ __launch_bounds__(256) void k4_final(const float* __restrict__ labels,
                                                const float* __restrict__ b2,
                                                const float* __restrict__ c_attn,
                                                const float* __restrict__ c_pool,
                                                float* __restrict__ out) {
    __shared__ float red[256];
    int tid = threadIdx.x;
    float s = 0.f;
    for (int i = tid; i < Nn; i += 256) {
        float lg = b2[0];
#pragma unroll
        for (int q = 0; q < 8; q++) lg += g_part[i * 8 + q];
        float y = labels[i];
        float sp = (lg > 0.f) ? lg + log1pf(expf(-lg)) : log1pf(expf(lg));
        s += 2.0f * y * (sp - lg) + (1.0f - y) * sp;
    }
    red[tid] = s;
    __syncthreads();
    for (int st = 128; st; st >>= 1) {
        if (tid < st) red[tid] += red[tid + st];
        __syncthreads();
    }
    if (tid == 0) {
        float ca = c_attn[0], cp = c_pool[0];
        out[0] = red[0] / (float)Nn + ca * ca + cp * cp;
    }
}

static const int MMA_SMEM = 2 * 128 * SA * 2;
static const int K2_SMEM = MMA_SMEM + (8 * 128 + 2 * 128 + 3 * 128) * 4 + 128 * 4;
static const int PREP_SMEM = KC * SST64 * 4 * 2;

extern "C" void kernel_launch(void* const* d_in, const int* in_sizes, int n_in,
                              void* d_out, int out_size) {
    const float* E       = (const float*)d_in[0];
    const float* Wq      = (const float*)d_in[1];
    const float* Wk      = (const float*)d_in[2];
    const float* Wv      = (const float*)d_in[3];
    const float* c_attn  = (const float*)d_in[4];
    const float* c_pool  = (const float*)d_in[5];
    const float* W1      = (const float*)d_in[6];
    const float* b1      = (const float*)d_in[7];
    const float* W2      = (const float*)d_in[8];
    const float* b2      = (const float*)d_in[9];
    const float* demo    = (const float*)d_in[10];
    const float* ht      = (const float*)d_in[11];
    const float* et      = (const float*)d_in[12];
    const float* labels  = (const float*)d_in[13];
    const int*   codes   = (const int*)d_in[14];
    const int*   lengths = (const int*)d_in[15];
    float* out = (float*)d_out;

    cudaFuncSetAttribute(k1x, cudaFuncAttributeMaxDynamicSharedMemorySize, MMA_SMEM);
    cudaFuncSetAttribute(k2_attn, cudaFuncAttributeMaxDynamicSharedMemorySize, K2_SMEM);
    cudaFuncSetAttribute(k3b_H, cudaFuncAttributeMaxDynamicSharedMemorySize, MMA_SMEM);

    k_dummy<<<1, 32>>>();   // keeps k2 in the ncu capture slot
    k_prep<<<2691, 256, PREP_SMEM>>>(E, Wq, Wk, Wv, W1, demo, lengths);
    k1x<<<330, 256, MMA_SMEM>>>();
    k2_attn<<<Nn, 512, K2_SMEM>>>(codes, ht, et, lengths, c_attn, c_pool);
    k3b_H<<<dim3(16, 8), 256, MMA_SMEM>>>(b1, W2);
    k4_final<<<1, 256>>>(labels, b2, c_attn, c_pool, out);
}